// round 4
// baseline (speedup 1.0000x reference)
#include <cuda_runtime.h>
#include <math.h>

// Shapes (fixed by the problem)
#define B_ 8
#define S_ 1024
#define D_ 1024
#define H_ 16
#define DK_ 64
#define F_ 4096
#define MROWS (B_ * S_)          // 8192
#define QKV_N (3 * D_)           // 3072

// ---------------- scratch (device globals; no allocations allowed) ----------------
__device__ float g_Wqkv[D_ * QKV_N];        // packed [K=1024][N=3072] qkv weight
__device__ float g_bqkv[QKV_N];
__device__ float g_qkv [MROWS * QKV_N];     // [b,s][3072]: q|k|v, each [h, dk]
__device__ float g_att [MROWS * D_];        // attention out, concat head-major
__device__ float g_proj[MROWS * D_];
__device__ float g_x   [MROWS * D_];        // after LN1
__device__ float g_ffh [MROWS * F_];        // FFN hidden
__device__ float g_ff  [MROWS * D_];

union F2U { unsigned long long u; float2 f2; };

// ---------------- weight repack: Wq/Wk/Wv [H,D,DK] -> [D, 3072] ----------------
__global__ void repack_kernel(const float* __restrict__ Wq, const float* __restrict__ Wk,
                              const float* __restrict__ Wv, const float* __restrict__ bq,
                              const float* __restrict__ bk, const float* __restrict__ bv)
{
    int idx = blockIdx.x * 256 + threadIdx.x;
    if (idx >= D_ * QKV_N) return;
    int k = idx / QKV_N;
    int n = idx - k * QKV_N;
    int sec = n >> 10;          // 0=q,1=k,2=v
    int r   = n & 1023;         // h*64 + dk
    int h   = r >> 6;
    int dk  = r & 63;
    const float* W = (sec == 0) ? Wq : (sec == 1) ? Wk : Wv;
    g_Wqkv[idx] = W[(h * 1024 + k) * 64 + dk];   // [H,D,DK]
    if (idx < QKV_N) {
        const float* bb = (sec == 0) ? bq : (sec == 1) ? bk : bv;
        g_bqkv[idx] = bb[r];
    }
}

// ---------------- SGEMM: C[M,N] = A[M,K] @ B[K,N] + bias (opt ReLU) ----------------
// 128x128 tile, BK=16, 256 threads, 8x8 microtile, f32x2 packed FMA (2x fp32 rate).
__global__ void __launch_bounds__(256) sgemm_kernel(
    const float* __restrict__ A, const float* __restrict__ B,
    const float* __restrict__ bias, float* __restrict__ C,
    int M, int N, int K, int doRelu)
{
    __shared__ float As[16][128];   // transposed A tile: As[k][m]
    __shared__ float Bs[16][128];

    int tid = threadIdx.x;
    int tx = tid & 15, ty = tid >> 4;
    int bm = blockIdx.y << 7, bn = blockIdx.x << 7;

    unsigned long long acc[8][4];   // 8 rows x 4 packed col-pairs
#pragma unroll
    for (int i = 0; i < 8; i++)
#pragma unroll
        for (int jp = 0; jp < 4; jp++) acc[i][jp] = 0ull;

    for (int k0 = 0; k0 < K; k0 += 16) {
#pragma unroll
        for (int l = 0; l < 2; l++) {
            int idx = tid + (l << 8);
            int ar = idx >> 2, ac = (idx & 3) << 2;
            float4 av = *(const float4*)(A + (size_t)(bm + ar) * K + k0 + ac);
            As[ac + 0][ar] = av.x; As[ac + 1][ar] = av.y;
            As[ac + 2][ar] = av.z; As[ac + 3][ar] = av.w;
            int br = idx >> 5, bc = (idx & 31) << 2;
            *(float4*)(&Bs[br][bc]) = *(const float4*)(B + (size_t)(k0 + br) * N + bn + bc);
        }
        __syncthreads();
#pragma unroll
        for (int kk = 0; kk < 16; kk++) {
            float4 a0 = *(const float4*)(&As[kk][ty << 3]);
            float4 a1 = *(const float4*)(&As[kk][(ty << 3) + 4]);
            ulonglong2 bb0 = *(const ulonglong2*)(&Bs[kk][tx << 3]);
            ulonglong2 bb1 = *(const ulonglong2*)(&Bs[kk][(tx << 3) + 4]);
            float a[8] = {a0.x, a0.y, a0.z, a0.w, a1.x, a1.y, a1.z, a1.w};
            unsigned long long bp[4] = {bb0.x, bb0.y, bb1.x, bb1.y};
#pragma unroll
            for (int i = 0; i < 8; i++) {
                unsigned long long ad;
                asm("mov.b64 %0, {%1, %1};" : "=l"(ad) : "f"(a[i]));
#pragma unroll
                for (int jp = 0; jp < 4; jp++)
                    asm("fma.rn.f32x2 %0, %1, %2, %0;"
                        : "+l"(acc[i][jp]) : "l"(ad), "l"(bp[jp]));
            }
        }
        __syncthreads();
    }

    int row = bm + (ty << 3);
    int col = bn + (tx << 3);
    float4 bi0 = *(const float4*)(bias + col);
    float4 bi1 = *(const float4*)(bias + col + 4);
    float bi[8] = {bi0.x, bi0.y, bi0.z, bi0.w, bi1.x, bi1.y, bi1.z, bi1.w};
#pragma unroll
    for (int i = 0; i < 8; i++) {
        float r[8];
#pragma unroll
        for (int jp = 0; jp < 4; jp++) {
            F2U u; u.u = acc[i][jp];
            r[2 * jp] = u.f2.x; r[2 * jp + 1] = u.f2.y;
        }
#pragma unroll
        for (int j = 0; j < 8; j++) {
            r[j] += bi[j];
            if (doRelu) r[j] = fmaxf(r[j], 0.f);
        }
        float* cp = C + (size_t)(row + i) * N + col;
        *(float4*)cp       = make_float4(r[0], r[1], r[2], r[3]);
        *(float4*)(cp + 4) = make_float4(r[4], r[5], r[6], r[7]);
    }
}

// ---------------- flash attention: 64 q-rows/CTA, 64-key tiles, online softmax ----------------
// grid: (S/64, B*H), 256 threads. Dyn smem: Qs[64*64] Ss[64*64] Ks[64*65] Vs[64*65].
#define ATT_SMEM ((4096 * 2 + 4160 * 2) * 4)

__global__ void __launch_bounds__(256) attn_kernel(const float* __restrict__ qkv,
                                                   float* __restrict__ oc)
{
    extern __shared__ float sm[];
    float* Qs = sm;            // [64][64]
    float* Ss = sm + 4096;     // [64][64]
    float* Ks = sm + 8192;     // [64][65]
    float* Vs = Ks + 4160;     // [64][65]
    __shared__ float l_s[64];
    __shared__ float al_s[64];

    int tid = threadIdx.x;
    int tx = tid & 15, ty = tid >> 4;
    int bh = blockIdx.y;
    int b = bh >> 4, h = bh & 15;
    int q0 = blockIdx.x << 6;
    const float* base = qkv + (size_t)b * S_ * QKV_N + h * 64;

    // load Q tile (reused across all 16 key tiles)
#pragma unroll
    for (int l = 0; l < 4; l++) {
        int idx = tid + l * 256;
        int r = idx >> 4, c = (idx & 15) << 2;
        float4 v = *(const float4*)(base + (size_t)(q0 + r) * QKV_N + c);
        *(float4*)(Qs + r * 64 + c) = v;
    }

    float acc[4][4];
#pragma unroll
    for (int i = 0; i < 4; i++)
#pragma unroll
        for (int j = 0; j < 4; j++) acc[i][j] = 0.f;
    float my_m = -1e30f, my_l = 0.f;
    int srow = tid >> 2, sq = tid & 3;   // softmax: 4 threads per row
    __syncthreads();

    for (int t = 0; t < 16; t++) {
        // load K, V tiles
#pragma unroll
        for (int l = 0; l < 4; l++) {
            int idx = tid + l * 256;
            int r = idx >> 4, c = (idx & 15) << 2;
            const float* rp = base + (size_t)(t * 64 + r) * QKV_N + c;
            float4 kv = *(const float4*)(rp + 1024);
            float4 vv = *(const float4*)(rp + 2048);
            float* kd = Ks + r * 65 + c;
            kd[0] = kv.x; kd[1] = kv.y; kd[2] = kv.z; kd[3] = kv.w;
            float* vd = Vs + r * 65 + c;
            vd[0] = vv.x; vd[1] = vv.y; vd[2] = vv.z; vd[3] = vv.w;
        }
        __syncthreads();

        // S = (Q @ K^T) * scale  (each thread 4x4 of 64x64)
        float s[4][4];
#pragma unroll
        for (int i = 0; i < 4; i++)
#pragma unroll
            for (int j = 0; j < 4; j++) s[i][j] = 0.f;
#pragma unroll 8
        for (int kk = 0; kk < 64; kk++) {
            float a0 = Qs[(ty * 4 + 0) * 64 + kk];
            float a1 = Qs[(ty * 4 + 1) * 64 + kk];
            float a2 = Qs[(ty * 4 + 2) * 64 + kk];
            float a3 = Qs[(ty * 4 + 3) * 64 + kk];
            float b0 = Ks[(tx * 4 + 0) * 65 + kk];
            float b1 = Ks[(tx * 4 + 1) * 65 + kk];
            float b2 = Ks[(tx * 4 + 2) * 65 + kk];
            float b3 = Ks[(tx * 4 + 3) * 65 + kk];
            s[0][0] += a0 * b0; s[0][1] += a0 * b1; s[0][2] += a0 * b2; s[0][3] += a0 * b3;
            s[1][0] += a1 * b0; s[1][1] += a1 * b1; s[1][2] += a1 * b2; s[1][3] += a1 * b3;
            s[2][0] += a2 * b0; s[2][1] += a2 * b1; s[2][2] += a2 * b2; s[2][3] += a2 * b3;
            s[3][0] += a3 * b0; s[3][1] += a3 * b1; s[3][2] += a3 * b2; s[3][3] += a3 * b3;
        }
#pragma unroll
        for (int i = 0; i < 4; i++)
            *(float4*)(Ss + (ty * 4 + i) * 64 + tx * 4) =
                make_float4(s[i][0] * 0.125f, s[i][1] * 0.125f,
                            s[i][2] * 0.125f, s[i][3] * 0.125f);
        __syncthreads();

        // online softmax over this tile's 64 cols (4 threads x 16 cols per row)
        float sv[16];
        float tmax = -1e30f;
#pragma unroll
        for (int c = 0; c < 16; c++) {
            sv[c] = Ss[srow * 64 + sq * 16 + c];
            tmax = fmaxf(tmax, sv[c]);
        }
        tmax = fmaxf(tmax, __shfl_xor_sync(0xffffffffu, tmax, 1));
        tmax = fmaxf(tmax, __shfl_xor_sync(0xffffffffu, tmax, 2));
        float newm  = fmaxf(my_m, tmax);
        float alpha = __expf(my_m - newm);
        float tsum = 0.f;
#pragma unroll
        for (int c = 0; c < 16; c++) {
            float p = __expf(sv[c] - newm);
            Ss[srow * 64 + sq * 16 + c] = p;
            tsum += p;
        }
        tsum += __shfl_xor_sync(0xffffffffu, tsum, 1);
        tsum += __shfl_xor_sync(0xffffffffu, tsum, 2);
        my_l = my_l * alpha + tsum;
        my_m = newm;
        if (sq == 0) al_s[srow] = alpha;
        __syncthreads();

        // O = O*alpha + P @ V
        float al0 = al_s[ty * 4 + 0], al1 = al_s[ty * 4 + 1];
        float al2 = al_s[ty * 4 + 2], al3 = al_s[ty * 4 + 3];
#pragma unroll
        for (int j = 0; j < 4; j++) {
            acc[0][j] *= al0; acc[1][j] *= al1; acc[2][j] *= al2; acc[3][j] *= al3;
        }
#pragma unroll 8
        for (int kk = 0; kk < 64; kk++) {
            float p0 = Ss[(ty * 4 + 0) * 64 + kk];
            float p1 = Ss[(ty * 4 + 1) * 64 + kk];
            float p2 = Ss[(ty * 4 + 2) * 64 + kk];
            float p3 = Ss[(ty * 4 + 3) * 64 + kk];
            float v0 = Vs[kk * 65 + tx * 4 + 0];
            float v1 = Vs[kk * 65 + tx * 4 + 1];
            float v2 = Vs[kk * 65 + tx * 4 + 2];
            float v3 = Vs[kk * 65 + tx * 4 + 3];
            acc[0][0] += p0 * v0; acc[0][1] += p0 * v1; acc[0][2] += p0 * v2; acc[0][3] += p0 * v3;
            acc[1][0] += p1 * v0; acc[1][1] += p1 * v1; acc[1][2] += p1 * v2; acc[1][3] += p1 * v3;
            acc[2][0] += p2 * v0; acc[2][1] += p2 * v1; acc[2][2] += p2 * v2; acc[2][3] += p2 * v3;
            acc[3][0] += p3 * v0; acc[3][1] += p3 * v1; acc[3][2] += p3 * v2; acc[3][3] += p3 * v3;
        }
        __syncthreads();
    }

    if (sq == 0) l_s[srow] = my_l;
    __syncthreads();
#pragma unroll
    for (int i = 0; i < 4; i++) {
        float invl = 1.f / l_s[ty * 4 + i];
        // concat layout: out[(b*S+s)*1024 + h*64 + dk]  (head-major == torch.cat order)
        *(float4*)(oc + (size_t)(b * S_ + q0 + ty * 4 + i) * D_ + h * 64 + tx * 4) =
            make_float4(acc[i][0] * invl, acc[i][1] * invl,
                        acc[i][2] * invl, acc[i][3] * invl);
    }
}

// ---------------- fused residual + LayerNorm (row = 1024) ----------------
__global__ void __launch_bounds__(256) add_ln_kernel(
    const float* __restrict__ a, const float* __restrict__ b,
    const float* __restrict__ gamma, const float* __restrict__ beta,
    float* __restrict__ out)
{
    int row = blockIdx.x, tid = threadIdx.x;
    size_t off = (size_t)row * 1024 + (tid << 2);
    float4 va = *(const float4*)(a + off);
    float4 vb = *(const float4*)(b + off);
    float4 x = make_float4(va.x + vb.x, va.y + vb.y, va.z + vb.z, va.w + vb.w);
    float s  = x.x + x.y + x.z + x.w;
    float ss = x.x * x.x + x.y * x.y + x.z * x.z + x.w * x.w;
#pragma unroll
    for (int o = 16; o > 0; o >>= 1) {
        s  += __shfl_xor_sync(0xffffffffu, s, o);
        ss += __shfl_xor_sync(0xffffffffu, ss, o);
    }
    __shared__ float ws[8], wss[8], stats[2];
    int lane = tid & 31, wid = tid >> 5;
    if (lane == 0) { ws[wid] = s; wss[wid] = ss; }
    __syncthreads();
    if (tid == 0) {
        float SS = 0.f, SQ = 0.f;
#pragma unroll
        for (int w = 0; w < 8; w++) { SS += ws[w]; SQ += wss[w]; }
        float mean = SS * (1.f / 1024.f);
        float var  = SQ * (1.f / 1024.f) - mean * mean;
        stats[0] = mean;
        stats[1] = rsqrtf(var + 1e-5f);
    }
    __syncthreads();
    float mean = stats[0], rstd = stats[1];
    float4 g4  = *(const float4*)(gamma + (tid << 2));
    float4 be4 = *(const float4*)(beta  + (tid << 2));
    float4 o4;
    o4.x = (x.x - mean) * rstd * g4.x + be4.x;
    o4.y = (x.y - mean) * rstd * g4.y + be4.y;
    o4.z = (x.z - mean) * rstd * g4.z + be4.z;
    o4.w = (x.w - mean) * rstd * g4.w + be4.w;
    *(float4*)(out + off) = o4;
}

// ---------------- launch ----------------
extern "C" void kernel_launch(void* const* d_in, const int* in_sizes, int n_in,
                              void* d_out, int out_size)
{
    const float* src = (const float*)d_in[0];
    const float* Wq  = (const float*)d_in[1];
    const float* bq  = (const float*)d_in[2];
    const float* Wk  = (const float*)d_in[3];
    const float* bk  = (const float*)d_in[4];
    const float* Wv  = (const float*)d_in[5];
    const float* bv  = (const float*)d_in[6];
    const float* Wo  = (const float*)d_in[7];
    const float* bo  = (const float*)d_in[8];
    const float* g1  = (const float*)d_in[9];
    const float* be1 = (const float*)d_in[10];
    const float* W1  = (const float*)d_in[11];
    const float* b1  = (const float*)d_in[12];
    const float* W2  = (const float*)d_in[13];
    const float* b2  = (const float*)d_in[14];
    const float* g2  = (const float*)d_in[15];
    const float* be2 = (const float*)d_in[16];
    float* out = (float*)d_out;

    float *Wqkv, *bqkv, *qkv, *att, *proj, *x, *ffh, *ff;
    cudaGetSymbolAddress((void**)&Wqkv, g_Wqkv);
    cudaGetSymbolAddress((void**)&bqkv, g_bqkv);
    cudaGetSymbolAddress((void**)&qkv,  g_qkv);
    cudaGetSymbolAddress((void**)&att,  g_att);
    cudaGetSymbolAddress((void**)&proj, g_proj);
    cudaGetSymbolAddress((void**)&x,    g_x);
    cudaGetSymbolAddress((void**)&ffh,  g_ffh);
    cudaGetSymbolAddress((void**)&ff,   g_ff);

    cudaFuncSetAttribute(attn_kernel, cudaFuncAttributeMaxDynamicSharedMemorySize, ATT_SMEM);

    // 1. repack QKV weights -> [1024, 3072] (+ bias)
    repack_kernel<<<(D_ * QKV_N + 255) / 256, 256>>>(Wq, Wk, Wv, bq, bk, bv);
    // 2. fused QKV projection: [8192,1024] @ [1024,3072]
    sgemm_kernel<<<dim3(QKV_N / 128, MROWS / 128), 256>>>(src, Wqkv, bqkv, qkv,
                                                          MROWS, QKV_N, D_, 0);
    // 3. attention -> concat [8192, 1024]
    attn_kernel<<<dim3(S_ / 64, B_ * H_), 256, ATT_SMEM>>>(qkv, att);
    // 4. output projection
    sgemm_kernel<<<dim3(D_ / 128, MROWS / 128), 256>>>(att, Wo, bo, proj,
                                                       MROWS, D_, D_, 0);
    // 5. x = LN(src + proj)
    add_ln_kernel<<<MROWS, 256>>>(src, proj, g1, be1, x);
    // 6. hidden = relu(x @ W1 + b1)
    sgemm_kernel<<<dim3(F_ / 128, MROWS / 128), 256>>>(x, W1, b1, ffh,
                                                       MROWS, F_, D_, 1);
    // 7. ff = hidden @ W2 + b2
    sgemm_kernel<<<dim3(D_ / 128, MROWS / 128), 256>>>(ffh, W2, b2, ff,
                                                       MROWS, D_, F_, 0);
    // 8. out = LN(x + ff)
    add_ln_kernel<<<MROWS, 256>>>(x, ff, g2, be2, out);
}

// round 8
// speedup vs baseline: 1.7795x; 1.7795x over previous
#include <cuda_runtime.h>
#include <cuda_bf16.h>
#include <cstdint>
#include <math.h>

// Shapes (fixed)
#define B_ 8
#define S_ 1024
#define D_ 1024
#define H_ 16
#define DK_ 64
#define F_ 4096
#define MROWS (B_ * S_)          // 8192
#define QKV_N (3 * D_)           // 3072

// ================= scratch (device globals; no allocations allowed) =================
__device__ float g_bqkv[QKV_N];
__device__ float g_qkv [MROWS * QKV_N];     // [b,s][3072]: q|k|v each [h, dk] (f32, attention input)
__device__ float g_proj[MROWS * D_];
__device__ float g_x   [MROWS * D_];
__device__ float g_ff  [MROWS * D_];
// bf16 hi/lo split activations (A operands, [M][K] row-major)
__device__ __nv_bfloat16 g_src_hi[MROWS * D_];
__device__ __nv_bfloat16 g_src_lo[MROWS * D_];
__device__ __nv_bfloat16 g_att_hi[MROWS * D_];
__device__ __nv_bfloat16 g_att_lo[MROWS * D_];
__device__ __nv_bfloat16 g_x_hi  [MROWS * D_];
__device__ __nv_bfloat16 g_x_lo  [MROWS * D_];
__device__ __nv_bfloat16 g_ffh_hi[MROWS * F_];
__device__ __nv_bfloat16 g_ffh_lo[MROWS * F_];
// pre-transposed + bf16-split weights, [N][K] row-major (B operands)
__device__ __nv_bfloat16 g_Bqkv_hi[QKV_N * D_];
__device__ __nv_bfloat16 g_Bqkv_lo[QKV_N * D_];
__device__ __nv_bfloat16 g_Bo_hi  [D_ * D_];
__device__ __nv_bfloat16 g_Bo_lo  [D_ * D_];
__device__ __nv_bfloat16 g_B1_hi  [F_ * D_];
__device__ __nv_bfloat16 g_B1_lo  [F_ * D_];
__device__ __nv_bfloat16 g_B2_hi  [D_ * F_];
__device__ __nv_bfloat16 g_B2_lo  [D_ * F_];

// ================= helpers =================
__device__ __forceinline__ uint32_t smem_u32(const void* p) {
    uint32_t a;
    asm("{ .reg .u64 t; cvta.to.shared.u64 t, %1; cvt.u32.u64 %0, t; }" : "=r"(a) : "l"(p));
    return a;
}
__device__ __forceinline__ void cp16(uint32_t s, const void* g) {
    asm volatile("cp.async.cg.shared.global [%0], [%1], 16;" :: "r"(s), "l"(g));
}
#define CP_COMMIT() asm volatile("cp.async.commit_group;" ::: "memory")
#define CP_WAIT(n)  asm volatile("cp.async.wait_group %0;" :: "n"(n) : "memory")

#define LDM4(r, a) \
    asm volatile("ldmatrix.sync.aligned.m8n8.x4.shared.b16 {%0,%1,%2,%3}, [%4];" \
        : "=r"((r)[0]), "=r"((r)[1]), "=r"((r)[2]), "=r"((r)[3]) : "r"(a))

__device__ __forceinline__ void mma16816(float* c, const uint32_t* a, uint32_t b0, uint32_t b1) {
    asm volatile("mma.sync.aligned.m16n8k16.row.col.f32.bf16.bf16.f32 "
                 "{%0,%1,%2,%3}, {%4,%5,%6,%7}, {%8,%9}, {%0,%1,%2,%3};"
                 : "+f"(c[0]), "+f"(c[1]), "+f"(c[2]), "+f"(c[3])
                 : "r"(a[0]), "r"(a[1]), "r"(a[2]), "r"(a[3]), "r"(b0), "r"(b1));
}

// split a pair of f32 into packed bf16 hi-word and lo-word
__device__ __forceinline__ void split2(float a, float b, uint32_t& h, uint32_t& l) {
    __nv_bfloat16 ha = __float2bfloat16_rn(a), hb = __float2bfloat16_rn(b);
    __nv_bfloat16 la = __float2bfloat16_rn(a - __bfloat162float(ha));
    __nv_bfloat16 lb = __float2bfloat16_rn(b - __bfloat162float(hb));
    h = (uint32_t)__bfloat16_as_ushort(ha) | ((uint32_t)__bfloat16_as_ushort(hb) << 16);
    l = (uint32_t)__bfloat16_as_ushort(la) | ((uint32_t)__bfloat16_as_ushort(lb) << 16);
}

// ================= weight pre-pass: tiled transpose + bf16 hi/lo split =================
__global__ void __launch_bounds__(256) tsplit_kernel(
    const float* __restrict__ in, int R, int C,
    __nv_bfloat16* __restrict__ ohi, __nv_bfloat16* __restrict__ olo,
    int opitch, int orow_base, long in_batch_stride, int orow_batch)
{
    __shared__ float t[32][33];
    int z = blockIdx.z;
    in += (size_t)z * in_batch_stride;
    int r0 = blockIdx.y * 32, c0 = blockIdx.x * 32;
    int x = threadIdx.x, y = threadIdx.y;
#pragma unroll
    for (int i = 0; i < 4; i++)
        t[y + i * 8][x] = in[(size_t)(r0 + y + i * 8) * C + c0 + x];
    __syncthreads();
    int orow0 = orow_base + z * orow_batch + c0;
#pragma unroll
    for (int i = 0; i < 4; i++) {
        float v = t[x][y + i * 8];
        __nv_bfloat16 h = __float2bfloat16_rn(v);
        __nv_bfloat16 l = __float2bfloat16_rn(v - __bfloat162float(h));
        size_t o = (size_t)(orow0 + y + i * 8) * opitch + r0 + x;
        ohi[o] = h;
        olo[o] = l;
    }
}

__global__ void pack_bias_kernel(const float* __restrict__ bq, const float* __restrict__ bk,
                                 const float* __restrict__ bv)
{
    int n = blockIdx.x * 256 + threadIdx.x;
    if (n >= QKV_N) return;
    int sec = n >> 10, r = n & 1023;
    const float* b = (sec == 0) ? bq : (sec == 1) ? bk : bv;
    g_bqkv[n] = b[r];
}

// elementwise f32 -> bf16 hi/lo split (for src)
__global__ void split_kernel(const float* __restrict__ in,
                             __nv_bfloat16* __restrict__ hi, __nv_bfloat16* __restrict__ lo)
{
    size_t i = ((size_t)blockIdx.x * 256 + threadIdx.x) << 2;
    float4 v = *(const float4*)(in + i);
    uint32_t h01, l01, h23, l23;
    split2(v.x, v.y, h01, l01);
    split2(v.z, v.w, h23, l23);
    *(uint2*)(hi + i) = make_uint2(h01, h23);
    *(uint2*)(lo + i) = make_uint2(l01, l23);
}

// ================= mma.sync bf16x3 GEMM =================
// C[M,N] = (Ahi+Alo)[M,K] @ (Bhi+Blo)[N,K]^T, dropping lo*lo.  128x128x64 tile, 256 thr.
// SMEM row: 64 hi bf16 | 64 lo bf16 | 16B pad = 272B. A region then B region per stage.
#define ROWB 272
#define HALF_STAGE (128 * ROWB)          // 34816
#define STAGE_B (2 * HALF_STAGE)         // 69632
#define GEMM_SMEM (2 * STAGE_B)          // 139264

__device__ __forceinline__ void gload(uint32_t sb,
    const __nv_bfloat16* Ah, const __nv_bfloat16* Al,
    const __nv_bfloat16* Bh, const __nv_bfloat16* Bl,
    int K, int k0, int tid)
{
#pragma unroll
    for (int g = 0; g < 4; g++) {
        int item = tid + (g << 8);
        int row = item >> 3;
        int chB = (item & 7) << 4;               // byte chunk in row (0..112)
        size_t go = (size_t)row * K + k0 + (chB >> 1);
        uint32_t so = sb + row * ROWB + chB;
        cp16(so,                    Ah + go);
        cp16(so + 128,              Al + go);
        cp16(so + HALF_STAGE,       Bh + go);
        cp16(so + HALF_STAGE + 128, Bl + go);
    }
}

__global__ void __launch_bounds__(256) mma_gemm_kernel(
    const __nv_bfloat16* __restrict__ Ahi, const __nv_bfloat16* __restrict__ Alo,
    const __nv_bfloat16* __restrict__ Bhi, const __nv_bfloat16* __restrict__ Blo,
    const float* __restrict__ bias,
    float* __restrict__ Cf, __nv_bfloat16* __restrict__ Chi, __nv_bfloat16* __restrict__ Clo,
    int N, int K, int doRelu)
{
    extern __shared__ char sm[];
    uint32_t sb = smem_u32(sm);
    int tid = threadIdx.x, wid = tid >> 5, lane = tid & 31;
    int bm = blockIdx.y << 7, bn = blockIdx.x << 7;
    Ahi += (size_t)bm * K; Alo += (size_t)bm * K;
    Bhi += (size_t)bn * K; Blo += (size_t)bn * K;

    float acc[4][4][4];
#pragma unroll
    for (int mt = 0; mt < 4; mt++)
#pragma unroll
        for (int nt = 0; nt < 4; nt++)
#pragma unroll
            for (int r = 0; r < 4; r++) acc[mt][nt][r] = 0.f;

    int wm = (wid >> 2) << 6;    // 0 / 64
    int wn = (wid & 3) << 5;     // 0..96
    int lr = lane & 15;
    int lk = (lane >> 4) << 4;   // byte offset of k-half

    int niter = K >> 6;
    gload(sb, Ahi, Alo, Bhi, Blo, K, 0, tid);
    CP_COMMIT();

    for (int it = 0; it < niter; it++) {
        if (it + 1 < niter) {
            gload(sb + ((it + 1) & 1) * STAGE_B, Ahi, Alo, Bhi, Blo, K, (it + 1) << 6, tid);
            CP_COMMIT();
            CP_WAIT(1);
        } else {
            CP_WAIT(0);
        }
        __syncthreads();

        uint32_t stage = sb + (it & 1) * STAGE_B;
        uint32_t ab = stage + (wm + lr) * ROWB;
        uint32_t bb = stage + HALF_STAGE + (wn + lr) * ROWB;
#pragma unroll
        for (int j = 0; j < 4; j++) {
            uint32_t ko = (j << 5) + lk;
            uint32_t bh0[4], bh1[4], bl0[4], bl1[4];
            LDM4(bh0, bb + ko);
            LDM4(bh1, bb + 16 * ROWB + ko);
            LDM4(bl0, bb + ko + 128);
            LDM4(bl1, bb + 16 * ROWB + ko + 128);
#pragma unroll
            for (int mt = 0; mt < 4; mt++) {
                uint32_t ah[4], al[4];
                LDM4(ah, ab + mt * 16 * ROWB + ko);
                LDM4(al, ab + mt * 16 * ROWB + ko + 128);
                mma16816(acc[mt][0], ah, bh0[0], bh0[2]);
                mma16816(acc[mt][1], ah, bh0[1], bh0[3]);
                mma16816(acc[mt][2], ah, bh1[0], bh1[2]);
                mma16816(acc[mt][3], ah, bh1[1], bh1[3]);
                mma16816(acc[mt][0], ah, bl0[0], bl0[2]);
                mma16816(acc[mt][1], ah, bl0[1], bl0[3]);
                mma16816(acc[mt][2], ah, bl1[0], bl1[2]);
                mma16816(acc[mt][3], ah, bl1[1], bl1[3]);
                mma16816(acc[mt][0], al, bh0[0], bh0[2]);
                mma16816(acc[mt][1], al, bh0[1], bh0[3]);
                mma16816(acc[mt][2], al, bh1[0], bh1[2]);
                mma16816(acc[mt][3], al, bh1[1], bh1[3]);
            }
        }
        __syncthreads();
    }

    // ---- epilogue ----
    int orow = bm + wm + (lane >> 2);
    int ocol = bn + wn + ((lane & 3) << 1);
#pragma unroll
    for (int mt = 0; mt < 4; mt++) {
#pragma unroll
        for (int nt = 0; nt < 4; nt++) {
            int c = ocol + nt * 8;
            float2 bi = *(const float2*)(bias + c);
            float v0 = acc[mt][nt][0] + bi.x;
            float v1 = acc[mt][nt][1] + bi.y;
            float v2 = acc[mt][nt][2] + bi.x;
            float v3 = acc[mt][nt][3] + bi.y;
            if (doRelu) {
                v0 = fmaxf(v0, 0.f); v1 = fmaxf(v1, 0.f);
                v2 = fmaxf(v2, 0.f); v3 = fmaxf(v3, 0.f);
            }
            int r = orow + mt * 16;
            if (Cf) {
                *(float2*)(Cf + (size_t)r * N + c)       = make_float2(v0, v1);
                *(float2*)(Cf + (size_t)(r + 8) * N + c) = make_float2(v2, v3);
            }
            if (Chi) {
                uint32_t h01, l01, h23, l23;
                split2(v0, v1, h01, l01);
                split2(v2, v3, h23, l23);
                *(uint32_t*)(Chi + (size_t)r * N + c)       = h01;
                *(uint32_t*)(Clo + (size_t)r * N + c)       = l01;
                *(uint32_t*)(Chi + (size_t)(r + 8) * N + c) = h23;
                *(uint32_t*)(Clo + (size_t)(r + 8) * N + c) = l23;
            }
        }
    }
}

// ================= flash attention (f32 SIMT; outputs bf16 hi/lo split) =================
#define ATT_SMEM ((4096 * 2 + 4160 * 2) * 4)

__global__ void __launch_bounds__(256) attn_kernel(const float* __restrict__ qkv,
                                                   __nv_bfloat16* __restrict__ att_hi,
                                                   __nv_bfloat16* __restrict__ att_lo)
{
    extern __shared__ float smf[];
    float* Qs = smf;
    float* Ss = smf + 4096;
    float* Ks = smf + 8192;
    float* Vs = Ks + 4160;
    __shared__ float l_s[64];
    __shared__ float al_s[64];

    int tid = threadIdx.x;
    int tx = tid & 15, ty = tid >> 4;
    int bh = blockIdx.y;
    int b = bh >> 4, h = bh & 15;
    int q0 = blockIdx.x << 6;
    const float* base = qkv + (size_t)b * S_ * QKV_N + h * 64;

#pragma unroll
    for (int l = 0; l < 4; l++) {
        int idx = tid + l * 256;
        int r = idx >> 4, c = (idx & 15) << 2;
        float4 v = *(const float4*)(base + (size_t)(q0 + r) * QKV_N + c);
        *(float4*)(Qs + r * 64 + c) = v;
    }

    float acc[4][4];
#pragma unroll
    for (int i = 0; i < 4; i++)
#pragma unroll
        for (int j = 0; j < 4; j++) acc[i][j] = 0.f;
    float my_m = -1e30f, my_l = 0.f;
    int srow = tid >> 2, sq = tid & 3;
    __syncthreads();

    for (int t = 0; t < 16; t++) {
#pragma unroll
        for (int l = 0; l < 4; l++) {
            int idx = tid + l * 256;
            int r = idx >> 4, c = (idx & 15) << 2;
            const float* rp = base + (size_t)(t * 64 + r) * QKV_N + c;
            float4 kv = *(const float4*)(rp + 1024);
            float4 vv = *(const float4*)(rp + 2048);
            float* kd = Ks + r * 65 + c;
            kd[0] = kv.x; kd[1] = kv.y; kd[2] = kv.z; kd[3] = kv.w;
            float* vd = Vs + r * 65 + c;
            vd[0] = vv.x; vd[1] = vv.y; vd[2] = vv.z; vd[3] = vv.w;
        }
        __syncthreads();

        float s[4][4];
#pragma unroll
        for (int i = 0; i < 4; i++)
#pragma unroll
            for (int j = 0; j < 4; j++) s[i][j] = 0.f;
#pragma unroll 8
        for (int kk = 0; kk < 64; kk++) {
            float a0 = Qs[(ty * 4 + 0) * 64 + kk];
            float a1 = Qs[(ty * 4 + 1) * 64 + kk];
            float a2 = Qs[(ty * 4 + 2) * 64 + kk];
            float a3 = Qs[(ty * 4 + 3) * 64 + kk];
            float b0 = Ks[(tx * 4 + 0) * 65 + kk];
            float b1 = Ks[(tx * 4 + 1) * 65 + kk];
            float b2 = Ks[(tx * 4 + 2) * 65 + kk];
            float b3 = Ks[(tx * 4 + 3) * 65 + kk];
            s[0][0] += a0 * b0; s[0][1] += a0 * b1; s[0][2] += a0 * b2; s[0][3] += a0 * b3;
            s[1][0] += a1 * b0; s[1][1] += a1 * b1; s[1][2] += a1 * b2; s[1][3] += a1 * b3;
            s[2][0] += a2 * b0; s[2][1] += a2 * b1; s[2][2] += a2 * b2; s[2][3] += a2 * b3;
            s[3][0] += a3 * b0; s[3][1] += a3 * b1; s[3][2] += a3 * b2; s[3][3] += a3 * b3;
        }
#pragma unroll
        for (int i = 0; i < 4; i++)
            *(float4*)(Ss + (ty * 4 + i) * 64 + tx * 4) =
                make_float4(s[i][0] * 0.125f, s[i][1] * 0.125f,
                            s[i][2] * 0.125f, s[i][3] * 0.125f);
        __syncthreads();

        float sv[16];
        float tmax = -1e30f;
#pragma unroll
        for (int c = 0; c < 16; c++) {
            sv[c] = Ss[srow * 64 + sq * 16 + c];
            tmax = fmaxf(tmax, sv[c]);
        }
        tmax = fmaxf(tmax, __shfl_xor_sync(0xffffffffu, tmax, 1));
        tmax = fmaxf(tmax, __shfl_xor_sync(0xffffffffu, tmax, 2));
        float newm  = fmaxf(my_m, tmax);
        float alpha = __expf(my_m - newm);
        float tsum = 0.f;
#pragma unroll
        for (int c = 0; c < 16; c++) {
            float p = __expf(sv[c] - newm);
            Ss[srow * 64 + sq * 16 + c] = p;
            tsum += p;
        }
        tsum += __shfl_xor_sync(0xffffffffu, tsum, 1);
        tsum += __shfl_xor_sync(0xffffffffu, tsum, 2);
        my_l = my_l * alpha + tsum;
        my_m = newm;
        if (sq == 0) al_s[srow] = alpha;
        __syncthreads();

        float al0 = al_s[ty * 4 + 0], al1 = al_s[ty * 4 + 1];
        float al2 = al_s[ty * 4 + 2], al3 = al_s[ty * 4 + 3];
#pragma unroll
        for (int j = 0; j < 4; j++) {
            acc[0][j] *= al0; acc[1][j] *= al1; acc[2][j] *= al2; acc[3][j] *= al3;
        }
#pragma unroll 8
        for (int kk = 0; kk < 64; kk++) {
            float p0 = Ss[(ty * 4 + 0) * 64 + kk];
            float p1 = Ss[(ty * 4 + 1) * 64 + kk];
            float p2 = Ss[(ty * 4 + 2) * 64 + kk];
            float p3 = Ss[(ty * 4 + 3) * 64 + kk];
            float v0 = Vs[kk * 65 + tx * 4 + 0];
            float v1 = Vs[kk * 65 + tx * 4 + 1];
            float v2 = Vs[kk * 65 + tx * 4 + 2];
            float v3 = Vs[kk * 65 + tx * 4 + 3];
            acc[0][0] += p0 * v0; acc[0][1] += p0 * v1; acc[0][2] += p0 * v2; acc[0][3] += p0 * v3;
            acc[1][0] += p1 * v0; acc[1][1] += p1 * v1; acc[1][2] += p1 * v2; acc[1][3] += p1 * v3;
            acc[2][0] += p2 * v0; acc[2][1] += p2 * v1; acc[2][2] += p2 * v2; acc[2][3] += p2 * v3;
            acc[3][0] += p3 * v0; acc[3][1] += p3 * v1; acc[3][2] += p3 * v2; acc[3][3] += p3 * v3;
        }
        __syncthreads();
    }

    if (sq == 0) l_s[srow] = my_l;
    __syncthreads();
#pragma unroll
    for (int i = 0; i < 4; i++) {
        float invl = 1.f / l_s[ty * 4 + i];
        float o0 = acc[i][0] * invl, o1 = acc[i][1] * invl;
        float o2 = acc[i][2] * invl, o3 = acc[i][3] * invl;
        uint32_t h01, l01, h23, l23;
        split2(o0, o1, h01, l01);
        split2(o2, o3, h23, l23);
        size_t idx = (size_t)(b * S_ + q0 + ty * 4 + i) * D_ + h * 64 + tx * 4;
        *(uint2*)(att_hi + idx) = make_uint2(h01, h23);
        *(uint2*)(att_lo + idx) = make_uint2(l01, l23);
    }
}

// ================= fused residual + LayerNorm (row = 1024); optional bf16 split out =================
__global__ void __launch_bounds__(256) add_ln_kernel(
    const float* __restrict__ a, const float* __restrict__ b,
    const float* __restrict__ gamma, const float* __restrict__ beta,
    float* __restrict__ out,
    __nv_bfloat16* __restrict__ ohi, __nv_bfloat16* __restrict__ olo)
{
    int row = blockIdx.x, tid = threadIdx.x;
    size_t off = (size_t)row * 1024 + (tid << 2);
    float4 va = *(const float4*)(a + off);
    float4 vb = *(const float4*)(b + off);
    float4 x = make_float4(va.x + vb.x, va.y + vb.y, va.z + vb.z, va.w + vb.w);
    float s  = x.x + x.y + x.z + x.w;
    float ss = x.x * x.x + x.y * x.y + x.z * x.z + x.w * x.w;
#pragma unroll
    for (int o = 16; o > 0; o >>= 1) {
        s  += __shfl_xor_sync(0xffffffffu, s, o);
        ss += __shfl_xor_sync(0xffffffffu, ss, o);
    }
    __shared__ float ws[8], wss[8], stats[2];
    int lane = tid & 31, wid = tid >> 5;
    if (lane == 0) { ws[wid] = s; wss[wid] = ss; }
    __syncthreads();
    if (tid == 0) {
        float SS = 0.f, SQ = 0.f;
#pragma unroll
        for (int w = 0; w < 8; w++) { SS += ws[w]; SQ += wss[w]; }
        float mean = SS * (1.f / 1024.f);
        float var  = SQ * (1.f / 1024.f) - mean * mean;
        stats[0] = mean;
        stats[1] = rsqrtf(var + 1e-5f);
    }
    __syncthreads();
    float mean = stats[0], rstd = stats[1];
    float4 g4  = *(const float4*)(gamma + (tid << 2));
    float4 be4 = *(const float4*)(beta  + (tid << 2));
    float4 o4;
    o4.x = (x.x - mean) * rstd * g4.x + be4.x;
    o4.y = (x.y - mean) * rstd * g4.y + be4.y;
    o4.z = (x.z - mean) * rstd * g4.z + be4.z;
    o4.w = (x.w - mean) * rstd * g4.w + be4.w;
    *(float4*)(out + off) = o4;
    if (ohi) {
        uint32_t h01, l01, h23, l23;
        split2(o4.x, o4.y, h01, l01);
        split2(o4.z, o4.w, h23, l23);
        *(uint2*)(ohi + off) = make_uint2(h01, h23);
        *(uint2*)(olo + off) = make_uint2(l01, l23);
    }
}

// ================= launch =================
extern "C" void kernel_launch(void* const* d_in, const int* in_sizes, int n_in,
                              void* d_out, int out_size)
{
    const float* src = (const float*)d_in[0];
    const float* Wq  = (const float*)d_in[1];
    const float* bq  = (const float*)d_in[2];
    const float* Wk  = (const float*)d_in[3];
    const float* bk  = (const float*)d_in[4];
    const float* Wv  = (const float*)d_in[5];
    const float* bv  = (const float*)d_in[6];
    const float* Wo  = (const float*)d_in[7];
    const float* bo  = (const float*)d_in[8];
    const float* g1  = (const float*)d_in[9];
    const float* be1 = (const float*)d_in[10];
    const float* W1  = (const float*)d_in[11];
    const float* b1  = (const float*)d_in[12];
    const float* W2  = (const float*)d_in[13];
    const float* b2  = (const float*)d_in[14];
    const float* g2  = (const float*)d_in[15];
    const float* be2 = (const float*)d_in[16];
    float* out = (float*)d_out;

    float *bqkv, *qkv, *proj, *x, *ff;
    __nv_bfloat16 *sh, *sl, *ath, *atl, *xh, *xl, *fhh, *fhl;
    __nv_bfloat16 *Bqh, *Bql, *Boh, *Bol, *B1h, *B1l, *B2h, *B2l;
    cudaGetSymbolAddress((void**)&bqkv, g_bqkv);
    cudaGetSymbolAddress((void**)&qkv,  g_qkv);
    cudaGetSymbolAddress((void**)&proj, g_proj);
    cudaGetSymbolAddress((void**)&x,    g_x);
    cudaGetSymbolAddress((void**)&ff,   g_ff);
    cudaGetSymbolAddress((void**)&sh,  g_src_hi);
    cudaGetSymbolAddress((void**)&sl,  g_src_lo);
    cudaGetSymbolAddress((void**)&ath, g_att_hi);
    cudaGetSymbolAddress((void**)&atl, g_att_lo);
    cudaGetSymbolAddress((void**)&xh,  g_x_hi);
    cudaGetSymbolAddress((void**)&xl,  g_x_lo);
    cudaGetSymbolAddress((void**)&fhh, g_ffh_hi);
    cudaGetSymbolAddress((void**)&fhl, g_ffh_lo);
    cudaGetSymbolAddress((void**)&Bqh, g_Bqkv_hi);
    cudaGetSymbolAddress((void**)&Bql, g_Bqkv_lo);
    cudaGetSymbolAddress((void**)&Boh, g_Bo_hi);
    cudaGetSymbolAddress((void**)&Bol, g_Bo_lo);
    cudaGetSymbolAddress((void**)&B1h, g_B1_hi);
    cudaGetSymbolAddress((void**)&B1l, g_B1_lo);
    cudaGetSymbolAddress((void**)&B2h, g_B2_hi);
    cudaGetSymbolAddress((void**)&B2l, g_B2_lo);

    cudaFuncSetAttribute(attn_kernel, cudaFuncAttributeMaxDynamicSharedMemorySize, ATT_SMEM);
    cudaFuncSetAttribute(mma_gemm_kernel, cudaFuncAttributeMaxDynamicSharedMemorySize, GEMM_SMEM);

    dim3 tb(32, 8);
    // pre-pass: biases, weight transpose+split, src split
    pack_bias_kernel<<<(QKV_N + 255) / 256, 256>>>(bq, bk, bv);
    tsplit_kernel<<<dim3(2, 32, 16), tb>>>(Wq, 1024, 64, Bqh, Bql, 1024, 0,    1024L * 64, 64);
    tsplit_kernel<<<dim3(2, 32, 16), tb>>>(Wk, 1024, 64, Bqh, Bql, 1024, 1024, 1024L * 64, 64);
    tsplit_kernel<<<dim3(2, 32, 16), tb>>>(Wv, 1024, 64, Bqh, Bql, 1024, 2048, 1024L * 64, 64);
    tsplit_kernel<<<dim3(32, 32, 1),  tb>>>(Wo, 1024, 1024, Boh, Bol, 1024, 0, 0, 0);
    tsplit_kernel<<<dim3(128, 32, 1), tb>>>(W1, 1024, 4096, B1h, B1l, 1024, 0, 0, 0);
    tsplit_kernel<<<dim3(32, 128, 1), tb>>>(W2, 4096, 1024, B2h, B2l, 4096, 0, 0, 0);
    split_kernel<<<MROWS * D_ / 1024, 256>>>(src, sh, sl);

    // 1. fused QKV projection: [8192,1024] @ [1024,3072] -> qkv f32
    mma_gemm_kernel<<<dim3(QKV_N / 128, MROWS / 128), 256, GEMM_SMEM>>>(
        sh, sl, Bqh, Bql, bqkv, qkv, nullptr, nullptr, QKV_N, D_, 0);
    // 2. attention -> att hi/lo splits
    attn_kernel<<<dim3(S_ / 64, B_ * H_), 256, ATT_SMEM>>>(qkv, ath, atl);
    // 3. output projection -> proj f32
    mma_gemm_kernel<<<dim3(D_ / 128, MROWS / 128), 256, GEMM_SMEM>>>(
        ath, atl, Boh, Bol, bo, proj, nullptr, nullptr, D_, D_, 0);
    // 4. x = LN(src + proj), f32 + splits
    add_ln_kernel<<<MROWS, 256>>>(src, proj, g1, be1, x, xh, xl);
    // 5. hidden = relu(x @ W1 + b1) -> splits only
    mma_gemm_kernel<<<dim3(F_ / 128, MROWS / 128), 256, GEMM_SMEM>>>(
        xh, xl, B1h, B1l, b1, nullptr, fhh, fhl, F_, D_, 1);
    // 6. ff = hidden @ W2 + b2 -> f32
    mma_gemm_kernel<<<dim3(D_ / 128, MROWS / 128), 256, GEMM_SMEM>>>(
        fhh, fhl, B2h, B2l, b2, ff, nullptr, nullptr, D_, F_, 0);
    // 7. out = LN(x + ff)
    add_ln_kernel<<<MROWS, 256>>>(x, ff, g2, be2, out, nullptr, nullptr);
}

// round 9
// speedup vs baseline: 3.0217x; 1.6980x over previous
#include <cuda_runtime.h>
#include <cuda_fp16.h>
#include <cstdint>
#include <math.h>

// Shapes (fixed)
#define B_ 8
#define S_ 1024
#define D_ 1024
#define H_ 16
#define DK_ 64
#define F_ 4096
#define MROWS (B_ * S_)          // 8192
#define QKV_N (3 * D_)           // 3072

// ================= scratch (device globals; no allocations allowed) =================
__device__ float g_bqkv[QKV_N];
__device__ float g_qkv [MROWS * QKV_N];     // f32, attention input
__device__ float g_proj[MROWS * D_];
__device__ float g_x   [MROWS * D_];
__device__ float g_ff  [MROWS * D_];
// fp16 activations (A operands, [M][K] row-major)
__device__ __half g_src_h[MROWS * D_];
__device__ __half g_att_h[MROWS * D_];
__device__ __half g_x_h  [MROWS * D_];
__device__ __half g_ffh_h[MROWS * F_];
// pre-transposed fp16 weights, [N][K] row-major (B operands)
__device__ __half g_Bqkv[QKV_N * D_];
__device__ __half g_Bo  [D_ * D_];
__device__ __half g_B1  [F_ * D_];
__device__ __half g_B2  [D_ * F_];

// ================= helpers =================
__device__ __forceinline__ uint32_t smem_u32(const void* p) {
    uint32_t a;
    asm("{ .reg .u64 t; cvta.to.shared.u64 t, %1; cvt.u32.u64 %0, t; }" : "=r"(a) : "l"(p));
    return a;
}
__device__ __forceinline__ void cp16(uint32_t s, const void* g) {
    asm volatile("cp.async.cg.shared.global [%0], [%1], 16;" :: "r"(s), "l"(g));
}
#define CP_COMMIT() asm volatile("cp.async.commit_group;" ::: "memory")
#define CP_WAIT(n)  asm volatile("cp.async.wait_group %0;" :: "n"(n) : "memory")

#define LDM4(r, a) \
    asm volatile("ldmatrix.sync.aligned.m8n8.x4.shared.b16 {%0,%1,%2,%3}, [%4];" \
        : "=r"((r)[0]), "=r"((r)[1]), "=r"((r)[2]), "=r"((r)[3]) : "r"(a))

__device__ __forceinline__ void mma16816(float* c, const uint32_t* a, uint32_t b0, uint32_t b1) {
    asm volatile("mma.sync.aligned.m16n8k16.row.col.f32.f16.f16.f32 "
                 "{%0,%1,%2,%3}, {%4,%5,%6,%7}, {%8,%9}, {%0,%1,%2,%3};"
                 : "+f"(c[0]), "+f"(c[1]), "+f"(c[2]), "+f"(c[3])
                 : "r"(a[0]), "r"(a[1]), "r"(a[2]), "r"(a[3]), "r"(b0), "r"(b1));
}

// ================= weight pre-pass: tiled transpose + fp16 convert =================
__global__ void __launch_bounds__(256) tsplit_kernel(
    const float* __restrict__ in, int R, int C,
    __half* __restrict__ oh,
    int opitch, int orow_base, long in_batch_stride, int orow_batch)
{
    __shared__ float t[32][33];
    int z = blockIdx.z;
    in += (size_t)z * in_batch_stride;
    int r0 = blockIdx.y * 32, c0 = blockIdx.x * 32;
    int x = threadIdx.x, y = threadIdx.y;
#pragma unroll
    for (int i = 0; i < 4; i++)
        t[y + i * 8][x] = in[(size_t)(r0 + y + i * 8) * C + c0 + x];
    __syncthreads();
    int orow0 = orow_base + z * orow_batch + c0;
#pragma unroll
    for (int i = 0; i < 4; i++) {
        float v = t[x][y + i * 8];
        oh[(size_t)(orow0 + y + i * 8) * opitch + r0 + x] = __float2half_rn(v);
    }
}

__global__ void pack_bias_kernel(const float* __restrict__ bq, const float* __restrict__ bk,
                                 const float* __restrict__ bv)
{
    int n = blockIdx.x * 256 + threadIdx.x;
    if (n >= QKV_N) return;
    int sec = n >> 10, r = n & 1023;
    const float* b = (sec == 0) ? bq : (sec == 1) ? bk : bv;
    g_bqkv[n] = b[r];
}

// elementwise f32 -> fp16 (for src)
__global__ void tohalf_kernel(const float* __restrict__ in, __half* __restrict__ oh)
{
    size_t i = ((size_t)blockIdx.x * 256 + threadIdx.x) << 2;
    float4 v = *(const float4*)(in + i);
    *(__half2*)(oh + i)     = __floats2half2_rn(v.x, v.y);
    *(__half2*)(oh + i + 2) = __floats2half2_rn(v.z, v.w);
}

// ================= mma.sync fp16 GEMM =================
// C[M,N] = A[M,K] @ B[N,K]^T.  128x128x64 tile, 256 thr, 2 CTAs/SM.
// SMEM row: 64 fp16 = 128B data + 16B pad = 144B. A region (128 rows), then B region.
#define ROWB 144
#define HALF_STAGE (128 * ROWB)          // 18432
#define STAGE_B (2 * HALF_STAGE)         // 36864
#define GEMM_SMEM (2 * STAGE_B)          // 73728

__device__ __forceinline__ void gload(uint32_t sb,
    const __half* __restrict__ A, const __half* __restrict__ Bw,
    int K, int k0, int tid)
{
#pragma unroll
    for (int g = 0; g < 8; g++) {
        int item = tid + (g << 8);
        int r = item >> 3;                   // 0..255
        int ch = (item & 7) << 4;            // byte chunk in row (0..112)
        if (r < 128)
            cp16(sb + r * ROWB + ch, A + (size_t)r * K + k0 + (ch >> 1));
        else
            cp16(sb + HALF_STAGE + (r - 128) * ROWB + ch,
                 Bw + (size_t)(r - 128) * K + k0 + (ch >> 1));
    }
}

__global__ void __launch_bounds__(256, 2) mma_gemm_kernel(
    const __half* __restrict__ A, const __half* __restrict__ Bw,
    const float* __restrict__ bias,
    float* __restrict__ Cf, __half* __restrict__ Ch,
    int N, int K, int doRelu)
{
    extern __shared__ char sm[];
    uint32_t sb = smem_u32(sm);
    int tid = threadIdx.x, wid = tid >> 5, lane = tid & 31;
    int bm = blockIdx.y << 7, bn = blockIdx.x << 7;
    A  += (size_t)bm * K;
    Bw += (size_t)bn * K;

    float acc[4][4][4];
#pragma unroll
    for (int mt = 0; mt < 4; mt++)
#pragma unroll
        for (int nt = 0; nt < 4; nt++)
#pragma unroll
            for (int r = 0; r < 4; r++) acc[mt][nt][r] = 0.f;

    int wm = (wid >> 2) << 6;    // 0 / 64
    int wn = (wid & 3) << 5;     // 0..96
    int lr = lane & 15;
    int lk = (lane >> 4) << 4;   // byte offset of k-half

    int niter = K >> 6;
    gload(sb, A, Bw, K, 0, tid);
    CP_COMMIT();

    for (int it = 0; it < niter; it++) {
        if (it + 1 < niter) {
            gload(sb + ((it + 1) & 1) * STAGE_B, A, Bw, K, (it + 1) << 6, tid);
            CP_COMMIT();
            CP_WAIT(1);
        } else {
            CP_WAIT(0);
        }
        __syncthreads();

        uint32_t stage = sb + (it & 1) * STAGE_B;
        uint32_t ab = stage + (wm + lr) * ROWB + lk;
        uint32_t bb = stage + HALF_STAGE + (wn + lr) * ROWB + lk;
#pragma unroll
        for (int j = 0; j < 4; j++) {
            uint32_t ko = j << 5;
            uint32_t b0[4], b1[4];
            LDM4(b0, bb + ko);
            LDM4(b1, bb + 16 * ROWB + ko);
#pragma unroll
            for (int mt = 0; mt < 4; mt++) {
                uint32_t a[4];
                LDM4(a, ab + mt * 16 * ROWB + ko);
                mma16816(acc[mt][0], a, b0[0], b0[2]);
                mma16816(acc[mt][1], a, b0[1], b0[3]);
                mma16816(acc[mt][2], a, b1[0], b1[2]);
                mma16816(acc[mt][3], a, b1[1], b1[3]);
            }
        }
        __syncthreads();
    }

    // ---- epilogue ----
    int orow = bm + wm + (lane >> 2);
    int ocol = bn + wn + ((lane & 3) << 1);
#pragma unroll
    for (int mt = 0; mt < 4; mt++) {
#pragma unroll
        for (int nt = 0; nt < 4; nt++) {
            int c = ocol + nt * 8;
            float2 bi = *(const float2*)(bias + c);
            float v0 = acc[mt][nt][0] + bi.x;
            float v1 = acc[mt][nt][1] + bi.y;
            float v2 = acc[mt][nt][2] + bi.x;
            float v3 = acc[mt][nt][3] + bi.y;
            if (doRelu) {
                v0 = fmaxf(v0, 0.f); v1 = fmaxf(v1, 0.f);
                v2 = fmaxf(v2, 0.f); v3 = fmaxf(v3, 0.f);
            }
            int r = orow + mt * 16;
            if (Cf) {
                *(float2*)(Cf + (size_t)r * N + c)       = make_float2(v0, v1);
                *(float2*)(Cf + (size_t)(r + 8) * N + c) = make_float2(v2, v3);
            }
            if (Ch) {
                *(__half2*)(Ch + (size_t)r * N + c)       = __floats2half2_rn(v0, v1);
                *(__half2*)(Ch + (size_t)(r + 8) * N + c) = __floats2half2_rn(v2, v3);
            }
        }
    }
}

// ================= flash attention (f32 SIMT; outputs fp16) =================
#define ATT_SMEM ((4096 * 2 + 4160 * 2) * 4)

__global__ void __launch_bounds__(256) attn_kernel(const float* __restrict__ qkv,
                                                   __half* __restrict__ att)
{
    extern __shared__ float smf[];
    float* Qs = smf;
    float* Ss = smf + 4096;
    float* Ks = smf + 8192;
    float* Vs = Ks + 4160;
    __shared__ float l_s[64];
    __shared__ float al_s[64];

    int tid = threadIdx.x;
    int tx = tid & 15, ty = tid >> 4;
    int bh = blockIdx.y;
    int b = bh >> 4, h = bh & 15;
    int q0 = blockIdx.x << 6;
    const float* base = qkv + (size_t)b * S_ * QKV_N + h * 64;

#pragma unroll
    for (int l = 0; l < 4; l++) {
        int idx = tid + l * 256;
        int r = idx >> 4, c = (idx & 15) << 2;
        float4 v = *(const float4*)(base + (size_t)(q0 + r) * QKV_N + c);
        *(float4*)(Qs + r * 64 + c) = v;
    }

    float acc[4][4];
#pragma unroll
    for (int i = 0; i < 4; i++)
#pragma unroll
        for (int j = 0; j < 4; j++) acc[i][j] = 0.f;
    float my_m = -1e30f, my_l = 0.f;
    int srow = tid >> 2, sq = tid & 3;
    __syncthreads();

    for (int t = 0; t < 16; t++) {
#pragma unroll
        for (int l = 0; l < 4; l++) {
            int idx = tid + l * 256;
            int r = idx >> 4, c = (idx & 15) << 2;
            const float* rp = base + (size_t)(t * 64 + r) * QKV_N + c;
            float4 kv = *(const float4*)(rp + 1024);
            float4 vv = *(const float4*)(rp + 2048);
            float* kd = Ks + r * 65 + c;
            kd[0] = kv.x; kd[1] = kv.y; kd[2] = kv.z; kd[3] = kv.w;
            float* vd = Vs + r * 65 + c;
            vd[0] = vv.x; vd[1] = vv.y; vd[2] = vv.z; vd[3] = vv.w;
        }
        __syncthreads();

        float s[4][4];
#pragma unroll
        for (int i = 0; i < 4; i++)
#pragma unroll
            for (int j = 0; j < 4; j++) s[i][j] = 0.f;
#pragma unroll 8
        for (int kk = 0; kk < 64; kk++) {
            float a0 = Qs[(ty * 4 + 0) * 64 + kk];
            float a1 = Qs[(ty * 4 + 1) * 64 + kk];
            float a2 = Qs[(ty * 4 + 2) * 64 + kk];
            float a3 = Qs[(ty * 4 + 3) * 64 + kk];
            float b0 = Ks[(tx * 4 + 0) * 65 + kk];
            float b1 = Ks[(tx * 4 + 1) * 65 + kk];
            float b2 = Ks[(tx * 4 + 2) * 65 + kk];
            float b3 = Ks[(tx * 4 + 3) * 65 + kk];
            s[0][0] += a0 * b0; s[0][1] += a0 * b1; s[0][2] += a0 * b2; s[0][3] += a0 * b3;
            s[1][0] += a1 * b0; s[1][1] += a1 * b1; s[1][2] += a1 * b2; s[1][3] += a1 * b3;
            s[2][0] += a2 * b0; s[2][1] += a2 * b1; s[2][2] += a2 * b2; s[2][3] += a2 * b3;
            s[3][0] += a3 * b0; s[3][1] += a3 * b1; s[3][2] += a3 * b2; s[3][3] += a3 * b3;
        }
#pragma unroll
        for (int i = 0; i < 4; i++)
            *(float4*)(Ss + (ty * 4 + i) * 64 + tx * 4) =
                make_float4(s[i][0] * 0.125f, s[i][1] * 0.125f,
                            s[i][2] * 0.125f, s[i][3] * 0.125f);
        __syncthreads();

        float sv[16];
        float tmax = -1e30f;
#pragma unroll
        for (int c = 0; c < 16; c++) {
            sv[c] = Ss[srow * 64 + sq * 16 + c];
            tmax = fmaxf(tmax, sv[c]);
        }
        tmax = fmaxf(tmax, __shfl_xor_sync(0xffffffffu, tmax, 1));
        tmax = fmaxf(tmax, __shfl_xor_sync(0xffffffffu, tmax, 2));
        float newm  = fmaxf(my_m, tmax);
        float alpha = __expf(my_m - newm);
        float tsum = 0.f;
#pragma unroll
        for (int c = 0; c < 16; c++) {
            float p = __expf(sv[c] - newm);
            Ss[srow * 64 + sq * 16 + c] = p;
            tsum += p;
        }
        tsum += __shfl_xor_sync(0xffffffffu, tsum, 1);
        tsum += __shfl_xor_sync(0xffffffffu, tsum, 2);
        my_l = my_l * alpha + tsum;
        my_m = newm;
        if (sq == 0) al_s[srow] = alpha;
        __syncthreads();

        float al0 = al_s[ty * 4 + 0], al1 = al_s[ty * 4 + 1];
        float al2 = al_s[ty * 4 + 2], al3 = al_s[ty * 4 + 3];
#pragma unroll
        for (int j = 0; j < 4; j++) {
            acc[0][j] *= al0; acc[1][j] *= al1; acc[2][j] *= al2; acc[3][j] *= al3;
        }
#pragma unroll 8
        for (int kk = 0; kk < 64; kk++) {
            float p0 = Ss[(ty * 4 + 0) * 64 + kk];
            float p1 = Ss[(ty * 4 + 1) * 64 + kk];
            float p2 = Ss[(ty * 4 + 2) * 64 + kk];
            float p3 = Ss[(ty * 4 + 3) * 64 + kk];
            float v0 = Vs[kk * 65 + tx * 4 + 0];
            float v1 = Vs[kk * 65 + tx * 4 + 1];
            float v2 = Vs[kk * 65 + tx * 4 + 2];
            float v3 = Vs[kk * 65 + tx * 4 + 3];
            acc[0][0] += p0 * v0; acc[0][1] += p0 * v1; acc[0][2] += p0 * v2; acc[0][3] += p0 * v3;
            acc[1][0] += p1 * v0; acc[1][1] += p1 * v1; acc[1][2] += p1 * v2; acc[1][3] += p1 * v3;
            acc[2][0] += p2 * v0; acc[2][1] += p2 * v1; acc[2][2] += p2 * v2; acc[2][3] += p2 * v3;
            acc[3][0] += p3 * v0; acc[3][1] += p3 * v1; acc[3][2] += p3 * v2; acc[3][3] += p3 * v3;
        }
        __syncthreads();
    }

    if (sq == 0) l_s[srow] = my_l;
    __syncthreads();
#pragma unroll
    for (int i = 0; i < 4; i++) {
        float invl = 1.f / l_s[ty * 4 + i];
        size_t idx = (size_t)(b * S_ + q0 + ty * 4 + i) * D_ + h * 64 + tx * 4;
        *(__half2*)(att + idx)     = __floats2half2_rn(acc[i][0] * invl, acc[i][1] * invl);
        *(__half2*)(att + idx + 2) = __floats2half2_rn(acc[i][2] * invl, acc[i][3] * invl);
    }
}

// ================= fused residual + LayerNorm (row = 1024); optional fp16 out =================
__global__ void __launch_bounds__(256) add_ln_kernel(
    const float* __restrict__ a, const float* __restrict__ b,
    const float* __restrict__ gamma, const float* __restrict__ beta,
    float* __restrict__ out, __half* __restrict__ oh)
{
    int row = blockIdx.x, tid = threadIdx.x;
    size_t off = (size_t)row * 1024 + (tid << 2);
    float4 va = *(const float4*)(a + off);
    float4 vb = *(const float4*)(b + off);
    float4 x = make_float4(va.x + vb.x, va.y + vb.y, va.z + vb.z, va.w + vb.w);
    float s  = x.x + x.y + x.z + x.w;
    float ss = x.x * x.x + x.y * x.y + x.z * x.z + x.w * x.w;
#pragma unroll
    for (int o = 16; o > 0; o >>= 1) {
        s  += __shfl_xor_sync(0xffffffffu, s, o);
        ss += __shfl_xor_sync(0xffffffffu, ss, o);
    }
    __shared__ float ws[8], wss[8], stats[2];
    int lane = tid & 31, wid = tid >> 5;
    if (lane == 0) { ws[wid] = s; wss[wid] = ss; }
    __syncthreads();
    if (tid == 0) {
        float SS = 0.f, SQ = 0.f;
#pragma unroll
        for (int w = 0; w < 8; w++) { SS += ws[w]; SQ += wss[w]; }
        float mean = SS * (1.f / 1024.f);
        float var  = SQ * (1.f / 1024.f) - mean * mean;
        stats[0] = mean;
        stats[1] = rsqrtf(var + 1e-5f);
    }
    __syncthreads();
    float mean = stats[0], rstd = stats[1];
    float4 g4  = *(const float4*)(gamma + (tid << 2));
    float4 be4 = *(const float4*)(beta  + (tid << 2));
    float4 o4;
    o4.x = (x.x - mean) * rstd * g4.x + be4.x;
    o4.y = (x.y - mean) * rstd * g4.y + be4.y;
    o4.z = (x.z - mean) * rstd * g4.z + be4.z;
    o4.w = (x.w - mean) * rstd * g4.w + be4.w;
    *(float4*)(out + off) = o4;
    if (oh) {
        *(__half2*)(oh + off)     = __floats2half2_rn(o4.x, o4.y);
        *(__half2*)(oh + off + 2) = __floats2half2_rn(o4.z, o4.w);
    }
}

// ================= launch =================
extern "C" void kernel_launch(void* const* d_in, const int* in_sizes, int n_in,
                              void* d_out, int out_size)
{
    const float* src = (const float*)d_in[0];
    const float* Wq  = (const float*)d_in[1];
    const float* bq  = (const float*)d_in[2];
    const float* Wk  = (const float*)d_in[3];
    const float* bk  = (const float*)d_in[4];
    const float* Wv  = (const float*)d_in[5];
    const float* bv  = (const float*)d_in[6];
    const float* Wo  = (const float*)d_in[7];
    const float* bo  = (const float*)d_in[8];
    const float* g1  = (const float*)d_in[9];
    const float* be1 = (const float*)d_in[10];
    const float* W1  = (const float*)d_in[11];
    const float* b1  = (const float*)d_in[12];
    const float* W2  = (const float*)d_in[13];
    const float* b2  = (const float*)d_in[14];
    const float* g2  = (const float*)d_in[15];
    const float* be2 = (const float*)d_in[16];
    float* out = (float*)d_out;

    float *bqkv, *qkv, *proj, *x, *ff;
    __half *sh, *ath, *xh, *fhh, *Bq, *Bo, *B1, *B2;
    cudaGetSymbolAddress((void**)&bqkv, g_bqkv);
    cudaGetSymbolAddress((void**)&qkv,  g_qkv);
    cudaGetSymbolAddress((void**)&proj, g_proj);
    cudaGetSymbolAddress((void**)&x,    g_x);
    cudaGetSymbolAddress((void**)&ff,   g_ff);
    cudaGetSymbolAddress((void**)&sh,  g_src_h);
    cudaGetSymbolAddress((void**)&ath, g_att_h);
    cudaGetSymbolAddress((void**)&xh,  g_x_h);
    cudaGetSymbolAddress((void**)&fhh, g_ffh_h);
    cudaGetSymbolAddress((void**)&Bq, g_Bqkv);
    cudaGetSymbolAddress((void**)&Bo, g_Bo);
    cudaGetSymbolAddress((void**)&B1, g_B1);
    cudaGetSymbolAddress((void**)&B2, g_B2);

    cudaFuncSetAttribute(attn_kernel, cudaFuncAttributeMaxDynamicSharedMemorySize, ATT_SMEM);
    cudaFuncSetAttribute(mma_gemm_kernel, cudaFuncAttributeMaxDynamicSharedMemorySize, GEMM_SMEM);

    dim3 tb(32, 8);
    // pre-pass: biases, weight transpose+fp16, src fp16
    pack_bias_kernel<<<(QKV_N + 255) / 256, 256>>>(bq, bk, bv);
    tsplit_kernel<<<dim3(2, 32, 16), tb>>>(Wq, 1024, 64, Bq, 1024, 0,    1024L * 64, 64);
    tsplit_kernel<<<dim3(2, 32, 16), tb>>>(Wk, 1024, 64, Bq, 1024, 1024, 1024L * 64, 64);
    tsplit_kernel<<<dim3(2, 32, 16), tb>>>(Wv, 1024, 64, Bq, 1024, 2048, 1024L * 64, 64);
    tsplit_kernel<<<dim3(32, 32, 1),  tb>>>(Wo, 1024, 1024, Bo, 1024, 0, 0, 0);
    tsplit_kernel<<<dim3(128, 32, 1), tb>>>(W1, 1024, 4096, B1, 1024, 0, 0, 0);
    tsplit_kernel<<<dim3(32, 128, 1), tb>>>(W2, 4096, 1024, B2, 4096, 0, 0, 0);
    tohalf_kernel<<<MROWS * D_ / 1024, 256>>>(src, sh);

    // 1. fused QKV projection: [8192,1024] @ [1024,3072] -> qkv f32
    mma_gemm_kernel<<<dim3(QKV_N / 128, MROWS / 128), 256, GEMM_SMEM>>>(
        sh, Bq, bqkv, qkv, nullptr, QKV_N, D_, 0);
    // 2. attention -> att fp16
    attn_kernel<<<dim3(S_ / 64, B_ * H_), 256, ATT_SMEM>>>(qkv, ath);
    // 3. output projection -> proj f32
    mma_gemm_kernel<<<dim3(D_ / 128, MROWS / 128), 256, GEMM_SMEM>>>(
        ath, Bo, bo, proj, nullptr, D_, D_, 0);
    // 4. x = LN(src + proj), f32 + fp16
    add_ln_kernel<<<MROWS, 256>>>(src, proj, g1, be1, x, xh);
    // 5. hidden = relu(x @ W1 + b1) -> fp16 only
    mma_gemm_kernel<<<dim3(F_ / 128, MROWS / 128), 256, GEMM_SMEM>>>(
        xh, B1, b1, nullptr, fhh, F_, D_, 1);
    // 6. ff = hidden @ W2 + b2 -> f32
    mma_gemm_kernel<<<dim3(D_ / 128, MROWS / 128), 256, GEMM_SMEM>>>(
        fhh, B2, b2, ff, nullptr, D_, F_, 0);
    // 7. out = LN(x + ff)
    add_ln_kernel<<<MROWS, 256>>>(x, ff, g2, be2, out, nullptr);
}

// round 10
// speedup vs baseline: 6.1441x; 2.0333x over previous
#include <cuda_runtime.h>
#include <cuda_fp16.h>
#include <cstdint>
#include <math.h>

// Shapes (fixed)
#define B_ 8
#define S_ 1024
#define D_ 1024
#define H_ 16
#define DK_ 64
#define F_ 4096
#define MROWS (B_ * S_)          // 8192
#define QKV_N (3 * D_)           // 3072

// ================= scratch (device globals; no allocations allowed) =================
__device__ float g_bqkv[QKV_N];
__device__ float g_proj[MROWS * D_];
__device__ float g_x   [MROWS * D_];
__device__ float g_ff  [MROWS * D_];
// fp16 activations
__device__ __half g_src_h[MROWS * D_];
__device__ __half g_qkvh [MROWS * QKV_N];       // q|k|v fp16, head-major per section
__device__ __half g_vt   [B_ * H_ * DK_ * S_];  // V^T per (b,h): [dk][s]
__device__ __half g_att_h[MROWS * D_];
__device__ __half g_x_h  [MROWS * D_];
__device__ __half g_ffh_h[MROWS * F_];
// pre-transposed fp16 weights, [N][K] row-major (B operands)
__device__ __half g_Bqkv[QKV_N * D_];
__device__ __half g_Bo  [D_ * D_];
__device__ __half g_B1  [F_ * D_];
__device__ __half g_B2  [D_ * F_];

// ================= helpers =================
__device__ __forceinline__ uint32_t smem_u32(const void* p) {
    uint32_t a;
    asm("{ .reg .u64 t; cvta.to.shared.u64 t, %1; cvt.u32.u64 %0, t; }" : "=r"(a) : "l"(p));
    return a;
}
__device__ __forceinline__ void cp16(uint32_t s, const void* g) {
    asm volatile("cp.async.cg.shared.global [%0], [%1], 16;" :: "r"(s), "l"(g));
}
#define CP_COMMIT() asm volatile("cp.async.commit_group;" ::: "memory")
#define CP_WAIT(n)  asm volatile("cp.async.wait_group %0;" :: "n"(n) : "memory")

#define LDM4(r, a) \
    asm volatile("ldmatrix.sync.aligned.m8n8.x4.shared.b16 {%0,%1,%2,%3}, [%4];" \
        : "=r"((r)[0]), "=r"((r)[1]), "=r"((r)[2]), "=r"((r)[3]) : "r"(a))

__device__ __forceinline__ void mma16816(float* c, const uint32_t* a, uint32_t b0, uint32_t b1) {
    asm volatile("mma.sync.aligned.m16n8k16.row.col.f32.f16.f16.f32 "
                 "{%0,%1,%2,%3}, {%4,%5,%6,%7}, {%8,%9}, {%0,%1,%2,%3};"
                 : "+f"(c[0]), "+f"(c[1]), "+f"(c[2]), "+f"(c[3])
                 : "r"(a[0]), "r"(a[1]), "r"(a[2]), "r"(a[3]), "r"(b0), "r"(b1));
}
__device__ __forceinline__ uint32_t pack_h2(float x, float y) {
    __half2 h = __floats2half2_rn(x, y);
    return *(uint32_t*)&h;
}

// ================= weight pre-pass: tiled transpose + fp16 convert =================
__global__ void __launch_bounds__(256) tsplit_kernel(
    const float* __restrict__ in, int R, int C,
    __half* __restrict__ oh,
    int opitch, int orow_base, long in_batch_stride, int orow_batch)
{
    __shared__ float t[32][33];
    int z = blockIdx.z;
    in += (size_t)z * in_batch_stride;
    int r0 = blockIdx.y * 32, c0 = blockIdx.x * 32;
    int x = threadIdx.x, y = threadIdx.y;
#pragma unroll
    for (int i = 0; i < 4; i++)
        t[y + i * 8][x] = in[(size_t)(r0 + y + i * 8) * C + c0 + x];
    __syncthreads();
    int orow0 = orow_base + z * orow_batch + c0;
#pragma unroll
    for (int i = 0; i < 4; i++) {
        float v = t[x][y + i * 8];
        oh[(size_t)(orow0 + y + i * 8) * opitch + r0 + x] = __float2half_rn(v);
    }
}

__global__ void pack_bias_kernel(const float* __restrict__ bq, const float* __restrict__ bk,
                                 const float* __restrict__ bv)
{
    int n = blockIdx.x * 256 + threadIdx.x;
    if (n >= QKV_N) return;
    int sec = n >> 10, r = n & 1023;
    const float* b = (sec == 0) ? bq : (sec == 1) ? bk : bv;
    g_bqkv[n] = b[r];
}

__global__ void tohalf_kernel(const float* __restrict__ in, __half* __restrict__ oh)
{
    size_t i = ((size_t)blockIdx.x * 256 + threadIdx.x) << 2;
    float4 v = *(const float4*)(in + i);
    *(__half2*)(oh + i)     = __floats2half2_rn(v.x, v.y);
    *(__half2*)(oh + i + 2) = __floats2half2_rn(v.z, v.w);
}

// V^T repack: qkvh v-section [s][dk] per (b,h) -> vt[bh][dk][s].  block (32,8)
__global__ void __launch_bounds__(256) vtrans_kernel(const __half* __restrict__ qkvh,
                                                     __half* __restrict__ vt)
{
    __shared__ __half t[32][33];
    int bh = blockIdx.z;
    int b = bh >> 4, h = bh & 15;
    int s0 = blockIdx.x * 32, d0 = blockIdx.y * 32;
    int x = threadIdx.x, y = threadIdx.y;
    const __half* in = qkvh + ((size_t)(b * 1024 + s0)) * QKV_N + 2048 + h * 64 + d0;
#pragma unroll
    for (int i = 0; i < 4; i++)
        t[y + i * 8][x] = in[(size_t)(y + i * 8) * QKV_N + x];
    __syncthreads();
    __half* o = vt + ((size_t)(bh * 64 + d0)) * 1024 + s0;
#pragma unroll
    for (int i = 0; i < 4; i++)
        o[(size_t)(y + i * 8) * 1024 + x] = t[x][y + i * 8];
}

// ================= mma.sync fp16 GEMM (unchanged from R9) =================
#define ROWB 144
#define HALF_STAGE (128 * ROWB)
#define STAGE_B (2 * HALF_STAGE)
#define GEMM_SMEM (2 * STAGE_B)

__device__ __forceinline__ void gload(uint32_t sb,
    const __half* __restrict__ A, const __half* __restrict__ Bw,
    int K, int k0, int tid)
{
#pragma unroll
    for (int g = 0; g < 8; g++) {
        int item = tid + (g << 8);
        int r = item >> 3;
        int ch = (item & 7) << 4;
        if (r < 128)
            cp16(sb + r * ROWB + ch, A + (size_t)r * K + k0 + (ch >> 1));
        else
            cp16(sb + HALF_STAGE + (r - 128) * ROWB + ch,
                 Bw + (size_t)(r - 128) * K + k0 + (ch >> 1));
    }
}

__global__ void __launch_bounds__(256, 2) mma_gemm_kernel(
    const __half* __restrict__ A, const __half* __restrict__ Bw,
    const float* __restrict__ bias,
    float* __restrict__ Cf, __half* __restrict__ Ch,
    int N, int K, int doRelu)
{
    extern __shared__ char sm[];
    uint32_t sb = smem_u32(sm);
    int tid = threadIdx.x, wid = tid >> 5, lane = tid & 31;
    int bm = blockIdx.y << 7, bn = blockIdx.x << 7;
    A  += (size_t)bm * K;
    Bw += (size_t)bn * K;

    float acc[4][4][4];
#pragma unroll
    for (int mt = 0; mt < 4; mt++)
#pragma unroll
        for (int nt = 0; nt < 4; nt++)
#pragma unroll
            for (int r = 0; r < 4; r++) acc[mt][nt][r] = 0.f;

    int wm = (wid >> 2) << 6;
    int wn = (wid & 3) << 5;
    int lr = lane & 15;
    int lk = (lane >> 4) << 4;

    int niter = K >> 6;
    gload(sb, A, Bw, K, 0, tid);
    CP_COMMIT();

    for (int it = 0; it < niter; it++) {
        if (it + 1 < niter) {
            gload(sb + ((it + 1) & 1) * STAGE_B, A, Bw, K, (it + 1) << 6, tid);
            CP_COMMIT();
            CP_WAIT(1);
        } else {
            CP_WAIT(0);
        }
        __syncthreads();

        uint32_t stage = sb + (it & 1) * STAGE_B;
        uint32_t ab = stage + (wm + lr) * ROWB + lk;
        uint32_t bb = stage + HALF_STAGE + (wn + lr) * ROWB + lk;
#pragma unroll
        for (int j = 0; j < 4; j++) {
            uint32_t ko = j << 5;
            uint32_t b0[4], b1[4];
            LDM4(b0, bb + ko);
            LDM4(b1, bb + 16 * ROWB + ko);
#pragma unroll
            for (int mt = 0; mt < 4; mt++) {
                uint32_t a[4];
                LDM4(a, ab + mt * 16 * ROWB + ko);
                mma16816(acc[mt][0], a, b0[0], b0[2]);
                mma16816(acc[mt][1], a, b0[1], b0[3]);
                mma16816(acc[mt][2], a, b1[0], b1[2]);
                mma16816(acc[mt][3], a, b1[1], b1[3]);
            }
        }
        __syncthreads();
    }

    int orow = bm + wm + (lane >> 2);
    int ocol = bn + wn + ((lane & 3) << 1);
#pragma unroll
    for (int mt = 0; mt < 4; mt++) {
#pragma unroll
        for (int nt = 0; nt < 4; nt++) {
            int c = ocol + nt * 8;
            float2 bi = *(const float2*)(bias + c);
            float v0 = acc[mt][nt][0] + bi.x;
            float v1 = acc[mt][nt][1] + bi.y;
            float v2 = acc[mt][nt][2] + bi.x;
            float v3 = acc[mt][nt][3] + bi.y;
            if (doRelu) {
                v0 = fmaxf(v0, 0.f); v1 = fmaxf(v1, 0.f);
                v2 = fmaxf(v2, 0.f); v3 = fmaxf(v3, 0.f);
            }
            int r = orow + mt * 16;
            if (Cf) {
                *(float2*)(Cf + (size_t)r * N + c)       = make_float2(v0, v1);
                *(float2*)(Cf + (size_t)(r + 8) * N + c) = make_float2(v2, v3);
            }
            if (Ch) {
                *(__half2*)(Ch + (size_t)r * N + c)       = __floats2half2_rn(v0, v1);
                *(__half2*)(Ch + (size_t)(r + 8) * N + c) = __floats2half2_rn(v2, v3);
            }
        }
    }
}

// ================= tensorized flash attention =================
// 128 thr / 64 q-rows per CTA; warp w owns rows 16w..16w+15.
// SMEM: Q[64][72h], K[2][64][72h], Vt[2][64][72h] fp16, 144B rows. 46080 B.
#define AROWB 144
#define ATILE (64 * AROWB)              // 9216
#define ATT_SMEM (5 * ATILE)

__global__ void __launch_bounds__(128) attn_kernel(
    const __half* __restrict__ qkvh, const __half* __restrict__ vt,
    __half* __restrict__ att)
{
    extern __shared__ char sma[];
    uint32_t sb = smem_u32(sma);
    const uint32_t Qs = sb;
    const uint32_t Ks = sb + ATILE;       // 2 buffers
    const uint32_t Vs = sb + 3 * ATILE;   // 2 buffers

    int tid = threadIdx.x, wid = tid >> 5, lane = tid & 31;
    int bh = blockIdx.y;
    int b = bh >> 4, h = bh & 15;
    int q0 = blockIdx.x << 6;
    int lr = lane & 15;
    int lk = (lane >> 4) << 4;

    const char* qbase = (const char*)(qkvh + ((size_t)(b * 1024 + q0)) * QKV_N + h * 64);
    const char* kbase = (const char*)(qkvh + ((size_t)(b * 1024)) * QKV_N + 1024 + h * 64);
    const char* vbase = (const char*)(vt + ((size_t)bh * 64) * 1024);

    // load Q + tile 0 of K,Vt
#pragma unroll
    for (int g = 0; g < 4; g++) {
        int c = tid + (g << 7);
        int r = c >> 3, ch = (c & 7) << 4;
        cp16(Qs + r * AROWB + ch, qbase + (size_t)r * (QKV_N * 2) + ch);
        cp16(Ks + r * AROWB + ch, kbase + (size_t)r * (QKV_N * 2) + ch);
        cp16(Vs + r * AROWB + ch, vbase + (size_t)r * 2048 + ch);
    }
    CP_COMMIT();
    CP_WAIT(0);
    __syncthreads();

    // hoist Q fragments (m16 x k64 per warp)
    uint32_t Qf[4][4];
    {
        uint32_t qa = Qs + (wid * 16 + lr) * AROWB + lk;
#pragma unroll
        for (int kk = 0; kk < 4; kk++) LDM4(Qf[kk], qa + kk * 32);
    }

    float Oacc[8][4];
#pragma unroll
    for (int n = 0; n < 8; n++)
#pragma unroll
        for (int r = 0; r < 4; r++) Oacc[n][r] = 0.f;
    float m0 = -1e30f, m1 = -1e30f, l0 = 0.f, l1 = 0.f;

    for (int t = 0; t < 16; t++) {
        if (t + 1 < 16) {
            uint32_t nb = (t + 1) & 1;
#pragma unroll
            for (int g = 0; g < 4; g++) {
                int c = tid + (g << 7);
                int r = c >> 3, ch = (c & 7) << 4;
                cp16(Ks + nb * ATILE + r * AROWB + ch,
                     kbase + (size_t)((t + 1) * 64 + r) * (QKV_N * 2) + ch);
                cp16(Vs + nb * ATILE + r * AROWB + ch,
                     vbase + (size_t)r * 2048 + (t + 1) * 128 + ch);
            }
            CP_COMMIT();
            CP_WAIT(1);
        } else {
            CP_WAIT(0);
        }
        __syncthreads();

        uint32_t cs = (t & 1) * ATILE;

        // S = Q @ K^T
        float Sacc[8][4];
#pragma unroll
        for (int n = 0; n < 8; n++)
#pragma unroll
            for (int r = 0; r < 4; r++) Sacc[n][r] = 0.f;
        {
            uint32_t kb = Ks + cs + lr * AROWB + lk;
#pragma unroll
            for (int nn = 0; nn < 4; nn++) {
#pragma unroll
                for (int kk = 0; kk < 4; kk++) {
                    uint32_t kf[4];
                    LDM4(kf, kb + nn * 16 * AROWB + kk * 32);
                    mma16816(Sacc[2 * nn],     Qf[kk], kf[0], kf[2]);
                    mma16816(Sacc[2 * nn + 1], Qf[kk], kf[1], kf[3]);
                }
            }
        }

        // online softmax (registers; rows r0=lane>>2 and r0+8; 4 lanes per row)
#pragma unroll
        for (int n = 0; n < 8; n++) {
            Sacc[n][0] *= 0.125f; Sacc[n][1] *= 0.125f;
            Sacc[n][2] *= 0.125f; Sacc[n][3] *= 0.125f;
        }
        float mx0 = -1e30f, mx1 = -1e30f;
#pragma unroll
        for (int n = 0; n < 8; n++) {
            mx0 = fmaxf(mx0, fmaxf(Sacc[n][0], Sacc[n][1]));
            mx1 = fmaxf(mx1, fmaxf(Sacc[n][2], Sacc[n][3]));
        }
        mx0 = fmaxf(mx0, __shfl_xor_sync(0xffffffffu, mx0, 1));
        mx0 = fmaxf(mx0, __shfl_xor_sync(0xffffffffu, mx0, 2));
        mx1 = fmaxf(mx1, __shfl_xor_sync(0xffffffffu, mx1, 1));
        mx1 = fmaxf(mx1, __shfl_xor_sync(0xffffffffu, mx1, 2));
        float nm0 = fmaxf(m0, mx0), nm1 = fmaxf(m1, mx1);
        float a0 = __expf(m0 - nm0), a1 = __expf(m1 - nm1);
        m0 = nm0; m1 = nm1;
        float sum0 = 0.f, sum1 = 0.f;
#pragma unroll
        for (int n = 0; n < 8; n++) {
            float p0 = __expf(Sacc[n][0] - nm0);
            float p1 = __expf(Sacc[n][1] - nm0);
            float p2 = __expf(Sacc[n][2] - nm1);
            float p3 = __expf(Sacc[n][3] - nm1);
            sum0 += p0 + p1; sum1 += p2 + p3;
            Sacc[n][0] = p0; Sacc[n][1] = p1; Sacc[n][2] = p2; Sacc[n][3] = p3;
        }
        sum0 += __shfl_xor_sync(0xffffffffu, sum0, 1);
        sum0 += __shfl_xor_sync(0xffffffffu, sum0, 2);
        sum1 += __shfl_xor_sync(0xffffffffu, sum1, 1);
        sum1 += __shfl_xor_sync(0xffffffffu, sum1, 2);
        l0 = l0 * a0 + sum0;
        l1 = l1 * a1 + sum1;
#pragma unroll
        for (int n = 0; n < 8; n++) {
            Oacc[n][0] *= a0; Oacc[n][1] *= a0;
            Oacc[n][2] *= a1; Oacc[n][3] *= a1;
        }

        // P -> fp16 A-fragments (accumulator layout == A layout for paired n-tiles)
        uint32_t Pa[4][4];
#pragma unroll
        for (int kk = 0; kk < 4; kk++) {
            Pa[kk][0] = pack_h2(Sacc[2 * kk][0],     Sacc[2 * kk][1]);
            Pa[kk][1] = pack_h2(Sacc[2 * kk][2],     Sacc[2 * kk][3]);
            Pa[kk][2] = pack_h2(Sacc[2 * kk + 1][0], Sacc[2 * kk + 1][1]);
            Pa[kk][3] = pack_h2(Sacc[2 * kk + 1][2], Sacc[2 * kk + 1][3]);
        }

        // O += P @ V  (B = Vt[dk][key])
        {
            uint32_t vb = Vs + cs + lr * AROWB + lk;
#pragma unroll
            for (int kk = 0; kk < 4; kk++) {
#pragma unroll
                for (int nn = 0; nn < 4; nn++) {
                    uint32_t vf[4];
                    LDM4(vf, vb + nn * 16 * AROWB + kk * 32);
                    mma16816(Oacc[2 * nn],     Pa[kk], vf[0], vf[2]);
                    mma16816(Oacc[2 * nn + 1], Pa[kk], vf[1], vf[3]);
                }
            }
        }
        __syncthreads();
    }

    // epilogue: normalize and write fp16 att (concat head-major layout)
    float invl0 = 1.f / l0, invl1 = 1.f / l1;
    int row = b * 1024 + q0 + wid * 16 + (lane >> 2);
    int col = h * 64 + ((lane & 3) << 1);
#pragma unroll
    for (int n = 0; n < 8; n++) {
        *(__half2*)(att + (size_t)row * 1024 + col + n * 8) =
            __floats2half2_rn(Oacc[n][0] * invl0, Oacc[n][1] * invl0);
        *(__half2*)(att + (size_t)(row + 8) * 1024 + col + n * 8) =
            __floats2half2_rn(Oacc[n][2] * invl1, Oacc[n][3] * invl1);
    }
}

// ================= fused residual + LayerNorm (row = 1024); optional fp16 out =================
__global__ void __launch_bounds__(256) add_ln_kernel(
    const float* __restrict__ a, const float* __restrict__ b,
    const float* __restrict__ gamma, const float* __restrict__ beta,
    float* __restrict__ out, __half* __restrict__ oh)
{
    int row = blockIdx.x, tid = threadIdx.x;
    size_t off = (size_t)row * 1024 + (tid << 2);
    float4 va = *(const float4*)(a + off);
    float4 vb = *(const float4*)(b + off);
    float4 x = make_float4(va.x + vb.x, va.y + vb.y, va.z + vb.z, va.w + vb.w);
    float s  = x.x + x.y + x.z + x.w;
    float ss = x.x * x.x + x.y * x.y + x.z * x.z + x.w * x.w;
#pragma unroll
    for (int o = 16; o > 0; o >>= 1) {
        s  += __shfl_xor_sync(0xffffffffu, s, o);
        ss += __shfl_xor_sync(0xffffffffu, ss, o);
    }
    __shared__ float ws[8], wss[8], stats[2];
    int lane = tid & 31, wid = tid >> 5;
    if (lane == 0) { ws[wid] = s; wss[wid] = ss; }
    __syncthreads();
    if (tid == 0) {
        float SS = 0.f, SQ = 0.f;
#pragma unroll
        for (int w = 0; w < 8; w++) { SS += ws[w]; SQ += wss[w]; }
        float mean = SS * (1.f / 1024.f);
        float var  = SQ * (1.f / 1024.f) - mean * mean;
        stats[0] = mean;
        stats[1] = rsqrtf(var + 1e-5f);
    }
    __syncthreads();
    float mean = stats[0], rstd = stats[1];
    float4 g4  = *(const float4*)(gamma + (tid << 2));
    float4 be4 = *(const float4*)(beta  + (tid << 2));
    float4 o4;
    o4.x = (x.x - mean) * rstd * g4.x + be4.x;
    o4.y = (x.y - mean) * rstd * g4.y + be4.y;
    o4.z = (x.z - mean) * rstd * g4.z + be4.z;
    o4.w = (x.w - mean) * rstd * g4.w + be4.w;
    *(float4*)(out + off) = o4;
    if (oh) {
        *(__half2*)(oh + off)     = __floats2half2_rn(o4.x, o4.y);
        *(__half2*)(oh + off + 2) = __floats2half2_rn(o4.z, o4.w);
    }
}

// ================= launch =================
extern "C" void kernel_launch(void* const* d_in, const int* in_sizes, int n_in,
                              void* d_out, int out_size)
{
    const float* src = (const float*)d_in[0];
    const float* Wq  = (const float*)d_in[1];
    const float* bq  = (const float*)d_in[2];
    const float* Wk  = (const float*)d_in[3];
    const float* bk  = (const float*)d_in[4];
    const float* Wv  = (const float*)d_in[5];
    const float* bv  = (const float*)d_in[6];
    const float* Wo  = (const float*)d_in[7];
    const float* bo  = (const float*)d_in[8];
    const float* g1  = (const float*)d_in[9];
    const float* be1 = (const float*)d_in[10];
    const float* W1  = (const float*)d_in[11];
    const float* b1  = (const float*)d_in[12];
    const float* W2  = (const float*)d_in[13];
    const float* b2  = (const float*)d_in[14];
    const float* g2  = (const float*)d_in[15];
    const float* be2 = (const float*)d_in[16];
    float* out = (float*)d_out;

    float *bqkv, *proj, *x, *ff;
    __half *sh, *qkvh, *vtp, *ath, *xh, *fhh, *Bq, *Bo, *B1, *B2;
    cudaGetSymbolAddress((void**)&bqkv, g_bqkv);
    cudaGetSymbolAddress((void**)&proj, g_proj);
    cudaGetSymbolAddress((void**)&x,    g_x);
    cudaGetSymbolAddress((void**)&ff,   g_ff);
    cudaGetSymbolAddress((void**)&sh,   g_src_h);
    cudaGetSymbolAddress((void**)&qkvh, g_qkvh);
    cudaGetSymbolAddress((void**)&vtp,  g_vt);
    cudaGetSymbolAddress((void**)&ath,  g_att_h);
    cudaGetSymbolAddress((void**)&xh,   g_x_h);
    cudaGetSymbolAddress((void**)&fhh,  g_ffh_h);
    cudaGetSymbolAddress((void**)&Bq, g_Bqkv);
    cudaGetSymbolAddress((void**)&Bo, g_Bo);
    cudaGetSymbolAddress((void**)&B1, g_B1);
    cudaGetSymbolAddress((void**)&B2, g_B2);

    cudaFuncSetAttribute(attn_kernel, cudaFuncAttributeMaxDynamicSharedMemorySize, ATT_SMEM);
    cudaFuncSetAttribute(mma_gemm_kernel, cudaFuncAttributeMaxDynamicSharedMemorySize, GEMM_SMEM);

    dim3 tb(32, 8);
    // pre-pass
    pack_bias_kernel<<<(QKV_N + 255) / 256, 256>>>(bq, bk, bv);
    tsplit_kernel<<<dim3(2, 32, 16), tb>>>(Wq, 1024, 64, Bq, 1024, 0,    1024L * 64, 64);
    tsplit_kernel<<<dim3(2, 32, 16), tb>>>(Wk, 1024, 64, Bq, 1024, 1024, 1024L * 64, 64);
    tsplit_kernel<<<dim3(2, 32, 16), tb>>>(Wv, 1024, 64, Bq, 1024, 2048, 1024L * 64, 64);
    tsplit_kernel<<<dim3(32, 32, 1),  tb>>>(Wo, 1024, 1024, Bo, 1024, 0, 0, 0);
    tsplit_kernel<<<dim3(128, 32, 1), tb>>>(W1, 1024, 4096, B1, 1024, 0, 0, 0);
    tsplit_kernel<<<dim3(32, 128, 1), tb>>>(W2, 4096, 1024, B2, 4096, 0, 0, 0);
    tohalf_kernel<<<MROWS * D_ / 1024, 256>>>(src, sh);

    // 1. fused QKV projection -> fp16 qkv
    mma_gemm_kernel<<<dim3(QKV_N / 128, MROWS / 128), 256, GEMM_SMEM>>>(
        sh, Bq, bqkv, nullptr, qkvh, QKV_N, D_, 0);
    // 1b. V^T repack
    vtrans_kernel<<<dim3(32, 2, 128), tb>>>(qkvh, vtp);
    // 2. tensorized attention -> att fp16
    attn_kernel<<<dim3(S_ / 64, B_ * H_), 128, ATT_SMEM>>>(qkvh, vtp, ath);
    // 3. output projection -> proj f32
    mma_gemm_kernel<<<dim3(D_ / 128, MROWS / 128), 256, GEMM_SMEM>>>(
        ath, Bo, bo, proj, nullptr, D_, D_, 0);
    // 4. x = LN(src + proj), f32 + fp16
    add_ln_kernel<<<MROWS, 256>>>(src, proj, g1, be1, x, xh);
    // 5. hidden = relu(x @ W1 + b1) -> fp16
    mma_gemm_kernel<<<dim3(F_ / 128, MROWS / 128), 256, GEMM_SMEM>>>(
        xh, B1, b1, nullptr, fhh, F_, D_, 1);
    // 6. ff = hidden @ W2 + b2 -> f32
    mma_gemm_kernel<<<dim3(D_ / 128, MROWS / 128), 256, GEMM_SMEM>>>(
        fhh, B2, b2, ff, nullptr, D_, F_, 0);
    // 7. out = LN(x + ff)
    add_ln_kernel<<<MROWS, 256>>>(x, ff, g2, be2, out, nullptr);
}

// round 11
// speedup vs baseline: 6.1704x; 1.0043x over previous
#include <cuda_runtime.h>
#include <cuda_fp16.h>
#include <cstdint>
#include <math.h>

// Shapes (fixed)
#define B_ 8
#define S_ 1024
#define D_ 1024
#define H_ 16
#define DK_ 64
#define F_ 4096
#define MROWS (B_ * S_)          // 8192
#define QKV_N (3 * D_)           // 3072

// ================= scratch (device globals; no allocations allowed) =================
__device__ float g_bqkv[QKV_N];
__device__ float g_proj[MROWS * D_];
__device__ float g_x   [MROWS * D_];
__device__ float g_ff  [MROWS * D_];
// fp16 activations
__device__ __half g_src_h[MROWS * D_];
__device__ __half g_qkvh [MROWS * QKV_N];       // q|k|v fp16, head-major per section
__device__ __half g_vt   [B_ * H_ * DK_ * S_];  // V^T per (b,h): [dk][s]
__device__ __half g_att_h[MROWS * D_];
__device__ __half g_x_h  [MROWS * D_];
__device__ __half g_ffh_h[MROWS * F_];
// pre-transposed fp16 weights, [N][K] row-major (B operands)
__device__ __half g_Bqkv[QKV_N * D_];
__device__ __half g_Bo  [D_ * D_];
__device__ __half g_B1  [F_ * D_];
__device__ __half g_B2  [D_ * F_];

// ================= helpers =================
__device__ __forceinline__ uint32_t smem_u32(const void* p) {
    uint32_t a;
    asm("{ .reg .u64 t; cvta.to.shared.u64 t, %1; cvt.u32.u64 %0, t; }" : "=r"(a) : "l"(p));
    return a;
}
__device__ __forceinline__ void cp16(uint32_t s, const void* g) {
    asm volatile("cp.async.cg.shared.global [%0], [%1], 16;" :: "r"(s), "l"(g));
}
#define CP_COMMIT() asm volatile("cp.async.commit_group;" ::: "memory")
#define CP_WAIT(n)  asm volatile("cp.async.wait_group %0;" :: "n"(n) : "memory")

#define LDM4(r, a) \
    asm volatile("ldmatrix.sync.aligned.m8n8.x4.shared.b16 {%0,%1,%2,%3}, [%4];" \
        : "=r"((r)[0]), "=r"((r)[1]), "=r"((r)[2]), "=r"((r)[3]) : "r"(a))

__device__ __forceinline__ void mma16816(float* c, const uint32_t* a, uint32_t b0, uint32_t b1) {
    asm volatile("mma.sync.aligned.m16n8k16.row.col.f32.f16.f16.f32 "
                 "{%0,%1,%2,%3}, {%4,%5,%6,%7}, {%8,%9}, {%0,%1,%2,%3};"
                 : "+f"(c[0]), "+f"(c[1]), "+f"(c[2]), "+f"(c[3])
                 : "r"(a[0]), "r"(a[1]), "r"(a[2]), "r"(a[3]), "r"(b0), "r"(b1));
}
__device__ __forceinline__ uint32_t pack_h2(float x, float y) {
    __half2 h = __floats2half2_rn(x, y);
    return *(uint32_t*)&h;
}

// ================= weight pre-pass: tiled transpose + fp16 convert =================
__global__ void __launch_bounds__(256) tsplit_kernel(
    const float* __restrict__ in, int R, int C,
    __half* __restrict__ oh,
    int opitch, int orow_base, long in_batch_stride, int orow_batch)
{
    __shared__ float t[32][33];
    int z = blockIdx.z;
    in += (size_t)z * in_batch_stride;
    int r0 = blockIdx.y * 32, c0 = blockIdx.x * 32;
    int x = threadIdx.x, y = threadIdx.y;
#pragma unroll
    for (int i = 0; i < 4; i++)
        t[y + i * 8][x] = in[(size_t)(r0 + y + i * 8) * C + c0 + x];
    __syncthreads();
    int orow0 = orow_base + z * orow_batch + c0;
#pragma unroll
    for (int i = 0; i < 4; i++) {
        float v = t[x][y + i * 8];
        oh[(size_t)(orow0 + y + i * 8) * opitch + r0 + x] = __float2half_rn(v);
    }
}

__global__ void pack_bias_kernel(const float* __restrict__ bq, const float* __restrict__ bk,
                                 const float* __restrict__ bv)
{
    int n = blockIdx.x * 256 + threadIdx.x;
    if (n >= QKV_N) return;
    int sec = n >> 10, r = n & 1023;
    const float* b = (sec == 0) ? bq : (sec == 1) ? bk : bv;
    g_bqkv[n] = b[r];
}

__global__ void tohalf_kernel(const float* __restrict__ in, __half* __restrict__ oh)
{
    size_t i = ((size_t)blockIdx.x * 256 + threadIdx.x) << 2;
    float4 v = *(const float4*)(in + i);
    *(__half2*)(oh + i)     = __floats2half2_rn(v.x, v.y);
    *(__half2*)(oh + i + 2) = __floats2half2_rn(v.z, v.w);
}

// V^T repack: qkvh v-section [s][dk] per (b,h) -> vt[bh][dk][s].  block (32,8)
__global__ void __launch_bounds__(256) vtrans_kernel(const __half* __restrict__ qkvh,
                                                     __half* __restrict__ vt)
{
    __shared__ __half t[32][33];
    int bh = blockIdx.z;
    int b = bh >> 4, h = bh & 15;
    int s0 = blockIdx.x * 32, d0 = blockIdx.y * 32;
    int x = threadIdx.x, y = threadIdx.y;
    const __half* in = qkvh + ((size_t)(b * 1024 + s0)) * QKV_N + 2048 + h * 64 + d0;
#pragma unroll
    for (int i = 0; i < 4; i++)
        t[y + i * 8][x] = in[(size_t)(y + i * 8) * QKV_N + x];
    __syncthreads();
    __half* o = vt + ((size_t)(bh * 64 + d0)) * 1024 + s0;
#pragma unroll
    for (int i = 0; i < 4; i++)
        o[(size_t)(y + i * 8) * 1024 + x] = t[x][y + i * 8];
}

// ================= mma.sync fp16 GEMM: 128 thr, 4 warps, 64x64 warp tile =================
#define ROWB 144
#define HALF_STAGE (128 * ROWB)
#define STAGE_B (2 * HALF_STAGE)
#define GEMM_SMEM (2 * STAGE_B)

__device__ __forceinline__ void gload(uint32_t sb,
    const __half* __restrict__ A, const __half* __restrict__ Bw,
    int K, int k0, int tid)
{
#pragma unroll
    for (int g = 0; g < 16; g++) {
        int item = tid + (g << 7);
        int r = item >> 3;                   // 0..255
        int ch = (item & 7) << 4;
        if (r < 128)
            cp16(sb + r * ROWB + ch, A + (size_t)r * K + k0 + (ch >> 1));
        else
            cp16(sb + HALF_STAGE + (r - 128) * ROWB + ch,
                 Bw + (size_t)(r - 128) * K + k0 + (ch >> 1));
    }
}

__global__ void __launch_bounds__(128, 2) mma_gemm_kernel(
    const __half* __restrict__ A, const __half* __restrict__ Bw,
    const float* __restrict__ bias,
    float* __restrict__ Cf, __half* __restrict__ Ch,
    int N, int K, int doRelu)
{
    extern __shared__ char sm[];
    uint32_t sb = smem_u32(sm);
    int tid = threadIdx.x, wid = tid >> 5, lane = tid & 31;
    int bm = blockIdx.y << 7, bn = blockIdx.x << 7;
    A  += (size_t)bm * K;
    Bw += (size_t)bn * K;

    float acc[4][8][4];
#pragma unroll
    for (int mt = 0; mt < 4; mt++)
#pragma unroll
        for (int nt = 0; nt < 8; nt++)
#pragma unroll
            for (int r = 0; r < 4; r++) acc[mt][nt][r] = 0.f;

    int wm = (wid >> 1) << 6;    // 0 / 64
    int wn = (wid & 1) << 6;     // 0 / 64
    int lr = lane & 15;
    int lk = (lane >> 4) << 4;

    int niter = K >> 6;
    gload(sb, A, Bw, K, 0, tid);
    CP_COMMIT();

    for (int it = 0; it < niter; it++) {
        if (it + 1 < niter) {
            gload(sb + ((it + 1) & 1) * STAGE_B, A, Bw, K, (it + 1) << 6, tid);
            CP_COMMIT();
            CP_WAIT(1);
        } else {
            CP_WAIT(0);
        }
        __syncthreads();

        uint32_t stage = sb + (it & 1) * STAGE_B;
        uint32_t ab = stage + (wm + lr) * ROWB + lk;
        uint32_t bb = stage + HALF_STAGE + (wn + lr) * ROWB + lk;
#pragma unroll
        for (int j = 0; j < 4; j++) {
            uint32_t ko = j << 5;
            uint32_t bf[4][4];
#pragma unroll
            for (int nb = 0; nb < 4; nb++)
                LDM4(bf[nb], bb + nb * 16 * ROWB + ko);
#pragma unroll
            for (int mt = 0; mt < 4; mt++) {
                uint32_t af[4];
                LDM4(af, ab + mt * 16 * ROWB + ko);
#pragma unroll
                for (int nb = 0; nb < 4; nb++) {
                    mma16816(acc[mt][2 * nb],     af, bf[nb][0], bf[nb][2]);
                    mma16816(acc[mt][2 * nb + 1], af, bf[nb][1], bf[nb][3]);
                }
            }
        }
        __syncthreads();
    }

    // ---- epilogue ----
    int orow = bm + wm + (lane >> 2);
    int ocol = bn + wn + ((lane & 3) << 1);
#pragma unroll
    for (int mt = 0; mt < 4; mt++) {
#pragma unroll
        for (int nt = 0; nt < 8; nt++) {
            int c = ocol + nt * 8;
            float2 bi = *(const float2*)(bias + c);
            float v0 = acc[mt][nt][0] + bi.x;
            float v1 = acc[mt][nt][1] + bi.y;
            float v2 = acc[mt][nt][2] + bi.x;
            float v3 = acc[mt][nt][3] + bi.y;
            if (doRelu) {
                v0 = fmaxf(v0, 0.f); v1 = fmaxf(v1, 0.f);
                v2 = fmaxf(v2, 0.f); v3 = fmaxf(v3, 0.f);
            }
            int r = orow + mt * 16;
            if (Cf) {
                *(float2*)(Cf + (size_t)r * N + c)       = make_float2(v0, v1);
                *(float2*)(Cf + (size_t)(r + 8) * N + c) = make_float2(v2, v3);
            }
            if (Ch) {
                *(__half2*)(Ch + (size_t)r * N + c)       = __floats2half2_rn(v0, v1);
                *(__half2*)(Ch + (size_t)(r + 8) * N + c) = __floats2half2_rn(v2, v3);
            }
        }
    }
}

// ================= tensorized flash attention: 128 q-rows/CTA, 256 thr =================
// SMEM: Q[128][72h] (18432B), K[2][64][72h], Vt[2][64][72h]. 55296 B.
#define AROWB 144
#define AQTILE (128 * AROWB)            // 18432
#define AKTILE (64 * AROWB)             // 9216
#define ATT_SMEM (AQTILE + 4 * AKTILE)

__global__ void __launch_bounds__(256) attn_kernel(
    const __half* __restrict__ qkvh, const __half* __restrict__ vt,
    __half* __restrict__ att)
{
    extern __shared__ char sma[];
    uint32_t sb = smem_u32(sma);
    const uint32_t Qs = sb;
    const uint32_t Ks = sb + AQTILE;           // 2 buffers
    const uint32_t Vs = sb + AQTILE + 2 * AKTILE;

    int tid = threadIdx.x, wid = tid >> 5, lane = tid & 31;
    int bh = blockIdx.y;
    int b = bh >> 4, h = bh & 15;
    int q0 = blockIdx.x << 7;
    int lr = lane & 15;
    int lk = (lane >> 4) << 4;

    const char* qbase = (const char*)(qkvh + ((size_t)(b * 1024 + q0)) * QKV_N + h * 64);
    const char* kbase = (const char*)(qkvh + ((size_t)(b * 1024)) * QKV_N + 1024 + h * 64);
    const char* vbase = (const char*)(vt + ((size_t)bh * 64) * 1024);

    // load Q (128 rows) + tile 0 of K,Vt (64 rows each)
#pragma unroll
    for (int g = 0; g < 4; g++) {
        int c = tid + (g << 8);
        int r = c >> 3, ch = (c & 7) << 4;
        cp16(Qs + r * AROWB + ch, qbase + (size_t)r * (QKV_N * 2) + ch);
    }
#pragma unroll
    for (int g = 0; g < 2; g++) {
        int c = tid + (g << 8);
        int r = c >> 3, ch = (c & 7) << 4;
        cp16(Ks + r * AROWB + ch, kbase + (size_t)r * (QKV_N * 2) + ch);
        cp16(Vs + r * AROWB + ch, vbase + (size_t)r * 2048 + ch);
    }
    CP_COMMIT();
    CP_WAIT(0);
    __syncthreads();

    // hoist Q fragments (m16 x k64 per warp)
    uint32_t Qf[4][4];
    {
        uint32_t qa = Qs + (wid * 16 + lr) * AROWB + lk;
#pragma unroll
        for (int kk = 0; kk < 4; kk++) LDM4(Qf[kk], qa + kk * 32);
    }

    float Oacc[8][4];
#pragma unroll
    for (int n = 0; n < 8; n++)
#pragma unroll
        for (int r = 0; r < 4; r++) Oacc[n][r] = 0.f;
    float m0 = -1e30f, m1 = -1e30f, l0 = 0.f, l1 = 0.f;

    for (int t = 0; t < 16; t++) {
        if (t + 1 < 16) {
            uint32_t nb = (t + 1) & 1;
#pragma unroll
            for (int g = 0; g < 2; g++) {
                int c = tid + (g << 8);
                int r = c >> 3, ch = (c & 7) << 4;
                cp16(Ks + nb * AKTILE + r * AROWB + ch,
                     kbase + (size_t)((t + 1) * 64 + r) * (QKV_N * 2) + ch);
                cp16(Vs + nb * AKTILE + r * AROWB + ch,
                     vbase + (size_t)r * 2048 + (t + 1) * 128 + ch);
            }
            CP_COMMIT();
            CP_WAIT(1);
        } else {
            CP_WAIT(0);
        }
        __syncthreads();

        uint32_t ck = (t & 1) * AKTILE;

        // S = Q @ K^T
        float Sacc[8][4];
#pragma unroll
        for (int n = 0; n < 8; n++)
#pragma unroll
            for (int r = 0; r < 4; r++) Sacc[n][r] = 0.f;
        {
            uint32_t kb = Ks + ck + lr * AROWB + lk;
#pragma unroll
            for (int nn = 0; nn < 4; nn++) {
#pragma unroll
                for (int kk = 0; kk < 4; kk++) {
                    uint32_t kf[4];
                    LDM4(kf, kb + nn * 16 * AROWB + kk * 32);
                    mma16816(Sacc[2 * nn],     Qf[kk], kf[0], kf[2]);
                    mma16816(Sacc[2 * nn + 1], Qf[kk], kf[1], kf[3]);
                }
            }
        }

        // online softmax (registers; rows r0=lane>>2 and r0+8; 4 lanes per row)
#pragma unroll
        for (int n = 0; n < 8; n++) {
            Sacc[n][0] *= 0.125f; Sacc[n][1] *= 0.125f;
            Sacc[n][2] *= 0.125f; Sacc[n][3] *= 0.125f;
        }
        float mx0 = -1e30f, mx1 = -1e30f;
#pragma unroll
        for (int n = 0; n < 8; n++) {
            mx0 = fmaxf(mx0, fmaxf(Sacc[n][0], Sacc[n][1]));
            mx1 = fmaxf(mx1, fmaxf(Sacc[n][2], Sacc[n][3]));
        }
        mx0 = fmaxf(mx0, __shfl_xor_sync(0xffffffffu, mx0, 1));
        mx0 = fmaxf(mx0, __shfl_xor_sync(0xffffffffu, mx0, 2));
        mx1 = fmaxf(mx1, __shfl_xor_sync(0xffffffffu, mx1, 1));
        mx1 = fmaxf(mx1, __shfl_xor_sync(0xffffffffu, mx1, 2));
        float nm0 = fmaxf(m0, mx0), nm1 = fmaxf(m1, mx1);
        float a0 = __expf(m0 - nm0), a1 = __expf(m1 - nm1);
        m0 = nm0; m1 = nm1;
        float sum0 = 0.f, sum1 = 0.f;
#pragma unroll
        for (int n = 0; n < 8; n++) {
            float p0 = __expf(Sacc[n][0] - nm0);
            float p1 = __expf(Sacc[n][1] - nm0);
            float p2 = __expf(Sacc[n][2] - nm1);
            float p3 = __expf(Sacc[n][3] - nm1);
            sum0 += p0 + p1; sum1 += p2 + p3;
            Sacc[n][0] = p0; Sacc[n][1] = p1; Sacc[n][2] = p2; Sacc[n][3] = p3;
        }
        sum0 += __shfl_xor_sync(0xffffffffu, sum0, 1);
        sum0 += __shfl_xor_sync(0xffffffffu, sum0, 2);
        sum1 += __shfl_xor_sync(0xffffffffu, sum1, 1);
        sum1 += __shfl_xor_sync(0xffffffffu, sum1, 2);
        l0 = l0 * a0 + sum0;
        l1 = l1 * a1 + sum1;
#pragma unroll
        for (int n = 0; n < 8; n++) {
            Oacc[n][0] *= a0; Oacc[n][1] *= a0;
            Oacc[n][2] *= a1; Oacc[n][3] *= a1;
        }

        // P -> fp16 A-fragments (accumulator layout == A layout for paired n-tiles)
        uint32_t Pa[4][4];
#pragma unroll
        for (int kk = 0; kk < 4; kk++) {
            Pa[kk][0] = pack_h2(Sacc[2 * kk][0],     Sacc[2 * kk][1]);
            Pa[kk][1] = pack_h2(Sacc[2 * kk][2],     Sacc[2 * kk][3]);
            Pa[kk][2] = pack_h2(Sacc[2 * kk + 1][0], Sacc[2 * kk + 1][1]);
            Pa[kk][3] = pack_h2(Sacc[2 * kk + 1][2], Sacc[2 * kk + 1][3]);
        }

        // O += P @ V  (B = Vt[dk][key])
        {
            uint32_t vb = Vs + ck + lr * AROWB + lk;
#pragma unroll
            for (int kk = 0; kk < 4; kk++) {
#pragma unroll
                for (int nn = 0; nn < 4; nn++) {
                    uint32_t vf[4];
                    LDM4(vf, vb + nn * 16 * AROWB + kk * 32);
                    mma16816(Oacc[2 * nn],     Pa[kk], vf[0], vf[2]);
                    mma16816(Oacc[2 * nn + 1], Pa[kk], vf[1], vf[3]);
                }
            }
        }
        __syncthreads();
    }

    // epilogue: normalize and write fp16 att (concat head-major layout)
    float invl0 = 1.f / l0, invl1 = 1.f / l1;
    int row = b * 1024 + q0 + wid * 16 + (lane >> 2);
    int col = h * 64 + ((lane & 3) << 1);
#pragma unroll
    for (int n = 0; n < 8; n++) {
        *(__half2*)(att + (size_t)row * 1024 + col + n * 8) =
            __floats2half2_rn(Oacc[n][0] * invl0, Oacc[n][1] * invl0);
        *(__half2*)(att + (size_t)(row + 8) * 1024 + col + n * 8) =
            __floats2half2_rn(Oacc[n][2] * invl1, Oacc[n][3] * invl1);
    }
}

// ================= fused residual + LayerNorm (row = 1024); optional fp16 out =================
__global__ void __launch_bounds__(256) add_ln_kernel(
    const float* __restrict__ a, const float* __restrict__ b,
    const float* __restrict__ gamma, const float* __restrict__ beta,
    float* __restrict__ out, __half* __restrict__ oh)
{
    int row = blockIdx.x, tid = threadIdx.x;
    size_t off = (size_t)row * 1024 + (tid << 2);
    float4 va = *(const float4*)(a + off);
    float4 vb = *(const float4*)(b + off);
    float4 x = make_float4(va.x + vb.x, va.y + vb.y, va.z + vb.z, va.w + vb.w);
    float s  = x.x + x.y + x.z + x.w;
    float ss = x.x * x.x + x.y * x.y + x.z * x.z + x.w * x.w;
#pragma unroll
    for (int o = 16; o > 0; o >>= 1) {
        s  += __shfl_xor_sync(0xffffffffu, s, o);
        ss += __shfl_xor_sync(0xffffffffu, ss, o);
    }
    __shared__ float ws[8], wss[8], stats[2];
    int lane = tid & 31, wid = tid >> 5;
    if (lane == 0) { ws[wid] = s; wss[wid] = ss; }
    __syncthreads();
    if (tid == 0) {
        float SS = 0.f, SQ = 0.f;
#pragma unroll
        for (int w = 0; w < 8; w++) { SS += ws[w]; SQ += wss[w]; }
        float mean = SS * (1.f / 1024.f);
        float var  = SQ * (1.f / 1024.f) - mean * mean;
        stats[0] = mean;
        stats[1] = rsqrtf(var + 1e-5f);
    }
    __syncthreads();
    float mean = stats[0], rstd = stats[1];
    float4 g4  = *(const float4*)(gamma + (tid << 2));
    float4 be4 = *(const float4*)(beta  + (tid << 2));
    float4 o4;
    o4.x = (x.x - mean) * rstd * g4.x + be4.x;
    o4.y = (x.y - mean) * rstd * g4.y + be4.y;
    o4.z = (x.z - mean) * rstd * g4.z + be4.z;
    o4.w = (x.w - mean) * rstd * g4.w + be4.w;
    *(float4*)(out + off) = o4;
    if (oh) {
        *(__half2*)(oh + off)     = __floats2half2_rn(o4.x, o4.y);
        *(__half2*)(oh + off + 2) = __floats2half2_rn(o4.z, o4.w);
    }
}

// ================= launch =================
extern "C" void kernel_launch(void* const* d_in, const int* in_sizes, int n_in,
                              void* d_out, int out_size)
{
    const float* src = (const float*)d_in[0];
    const float* Wq  = (const float*)d_in[1];
    const float* bq  = (const float*)d_in[2];
    const float* Wk  = (const float*)d_in[3];
    const float* bk  = (const float*)d_in[4];
    const float* Wv  = (const float*)d_in[5];
    const float* bv  = (const float*)d_in[6];
    const float* Wo  = (const float*)d_in[7];
    const float* bo  = (const float*)d_in[8];
    const float* g1  = (const float*)d_in[9];
    const float* be1 = (const float*)d_in[10];
    const float* W1  = (const float*)d_in[11];
    const float* b1  = (const float*)d_in[12];
    const float* W2  = (const float*)d_in[13];
    const float* b2  = (const float*)d_in[14];
    const float* g2  = (const float*)d_in[15];
    const float* be2 = (const float*)d_in[16];
    float* out = (float*)d_out;

    float *bqkv, *proj, *x, *ff;
    __half *sh, *qkvh, *vtp, *ath, *xh, *fhh, *Bq, *Bo, *B1, *B2;
    cudaGetSymbolAddress((void**)&bqkv, g_bqkv);
    cudaGetSymbolAddress((void**)&proj, g_proj);
    cudaGetSymbolAddress((void**)&x,    g_x);
    cudaGetSymbolAddress((void**)&ff,   g_ff);
    cudaGetSymbolAddress((void**)&sh,   g_src_h);
    cudaGetSymbolAddress((void**)&qkvh, g_qkvh);
    cudaGetSymbolAddress((void**)&vtp,  g_vt);
    cudaGetSymbolAddress((void**)&ath,  g_att_h);
    cudaGetSymbolAddress((void**)&xh,   g_x_h);
    cudaGetSymbolAddress((void**)&fhh,  g_ffh_h);
    cudaGetSymbolAddress((void**)&Bq, g_Bqkv);
    cudaGetSymbolAddress((void**)&Bo, g_Bo);
    cudaGetSymbolAddress((void**)&B1, g_B1);
    cudaGetSymbolAddress((void**)&B2, g_B2);

    cudaFuncSetAttribute(attn_kernel, cudaFuncAttributeMaxDynamicSharedMemorySize, ATT_SMEM);
    cudaFuncSetAttribute(mma_gemm_kernel, cudaFuncAttributeMaxDynamicSharedMemorySize, GEMM_SMEM);

    dim3 tb(32, 8);
    // pre-pass
    pack_bias_kernel<<<(QKV_N + 255) / 256, 256>>>(bq, bk, bv);
    tsplit_kernel<<<dim3(2, 32, 16), tb>>>(Wq, 1024, 64, Bq, 1024, 0,    1024L * 64, 64);
    tsplit_kernel<<<dim3(2, 32, 16), tb>>>(Wk, 1024, 64, Bq, 1024, 1024, 1024L * 64, 64);
    tsplit_kernel<<<dim3(2, 32, 16), tb>>>(Wv, 1024, 64, Bq, 1024, 2048, 1024L * 64, 64);
    tsplit_kernel<<<dim3(32, 32, 1),  tb>>>(Wo, 1024, 1024, Bo, 1024, 0, 0, 0);
    tsplit_kernel<<<dim3(128, 32, 1), tb>>>(W1, 1024, 4096, B1, 1024, 0, 0, 0);
    tsplit_kernel<<<dim3(32, 128, 1), tb>>>(W2, 4096, 1024, B2, 4096, 0, 0, 0);
    tohalf_kernel<<<MROWS * D_ / 1024, 256>>>(src, sh);

    // 1. fused QKV projection -> fp16 qkv
    mma_gemm_kernel<<<dim3(QKV_N / 128, MROWS / 128), 128, GEMM_SMEM>>>(
        sh, Bq, bqkv, nullptr, qkvh, QKV_N, D_, 0);
    // 1b. V^T repack
    vtrans_kernel<<<dim3(32, 2, 128), tb>>>(qkvh, vtp);
    // 2. tensorized attention -> att fp16
    attn_kernel<<<dim3(S_ / 128, B_ * H_), 256, ATT_SMEM>>>(qkvh, vtp, ath);
    // 3. output projection -> proj f32
    mma_gemm_kernel<<<dim3(D_ / 128, MROWS / 128), 128, GEMM_SMEM>>>(
        ath, Bo, bo, proj, nullptr, D_, D_, 0);
    // 4. x = LN(src + proj), f32 + fp16
    add_ln_kernel<<<MROWS, 256>>>(src, proj, g1, be1, x, xh);
    // 5. hidden = relu(x @ W1 + b1) -> fp16
    mma_gemm_kernel<<<dim3(F_ / 128, MROWS / 128), 128, GEMM_SMEM>>>(
        xh, B1, b1, nullptr, fhh, F_, D_, 1);
    // 6. ff = hidden @ W2 + b2 -> f32
    mma_gemm_kernel<<<dim3(D_ / 128, MROWS / 128), 128, GEMM_SMEM>>>(
        fhh, B2, b2, ff, nullptr, D_, F_, 0);
    // 7. out = LN(x + ff)
    add_ln_kernel<<<MROWS, 256>>>(x, ff, g2, be2, out, nullptr);
}